// round 7
// baseline (speedup 1.0000x reference)
#include <cuda_runtime.h>
#include <cuda_bf16.h>
#include <math.h>
#include <stdint.h>

#define B_SZ    2
#define N_SEQ   2048
#define D_MODEL 1024
#define N_HEADS 16
#define D_HEAD  64
#define M_ROWS  (B_SZ * N_SEQ)        // 4096
#define QKV_COLS (3 * D_MODEL)        // 3072
#define NT128   (N_SEQ / 128)         // 16
#define NPAIR128 (NT128 * (NT128 + 1) / 2)  // 136

// ---------------- scratch ---------------------------------------------------
__device__ float g_attn[(size_t)B_SZ * N_HEADS * N_SEQ * N_SEQ];      // fallback
__device__ __nv_bfloat16 g_xh[(size_t)M_ROWS * D_MODEL];
__device__ __nv_bfloat16 g_xl[(size_t)M_ROWS * D_MODEL];
__device__ __nv_bfloat16 g_qkvh[(size_t)M_ROWS * QKV_COLS];
__device__ __nv_bfloat16 g_qkvl[(size_t)M_ROWS * QKV_COLS];
__device__ __nv_bfloat16 g_ch[(size_t)M_ROWS * D_MODEL];
__device__ __nv_bfloat16 g_cl[(size_t)M_ROWS * D_MODEL];
__device__ __nv_bfloat16 g_wqh[(size_t)QKV_COLS * D_MODEL];   // [N][K]
__device__ __nv_bfloat16 g_wql[(size_t)QKV_COLS * D_MODEL];
__device__ __nv_bfloat16 g_woh[(size_t)D_MODEL * D_MODEL];
__device__ __nv_bfloat16 g_wol[(size_t)D_MODEL * D_MODEL];

// ---------------- warp-mma helpers ------------------------------------------
__device__ __forceinline__ uint32_t smem_u32(const void* p) {
    uint32_t a;
    asm("{ .reg .u64 t; cvta.to.shared.u64 t, %1; cvt.u32.u64 %0, t; }" : "=r"(a) : "l"(p));
    return a;
}
__device__ __forceinline__ void ldsm4(uint32_t* r, uint32_t a) {
    asm volatile("ldmatrix.sync.aligned.m8n8.x4.shared.b16 {%0,%1,%2,%3}, [%4];"
                 : "=r"(r[0]), "=r"(r[1]), "=r"(r[2]), "=r"(r[3]) : "r"(a));
}
__device__ __forceinline__ void ldsm4t(uint32_t* r, uint32_t a) {
    asm volatile("ldmatrix.sync.aligned.m8n8.x4.trans.shared.b16 {%0,%1,%2,%3}, [%4];"
                 : "=r"(r[0]), "=r"(r[1]), "=r"(r[2]), "=r"(r[3]) : "r"(a));
}
__device__ __forceinline__ void mma16816(float* c, const uint32_t* a, uint32_t b0, uint32_t b1) {
    asm volatile("mma.sync.aligned.m16n8k16.row.col.f32.bf16.bf16.f32 "
                 "{%0,%1,%2,%3}, {%4,%5,%6,%7}, {%8,%9}, {%0,%1,%2,%3};"
                 : "+f"(c[0]), "+f"(c[1]), "+f"(c[2]), "+f"(c[3])
                 : "r"(a[0]), "r"(a[1]), "r"(a[2]), "r"(a[3]), "r"(b0), "r"(b1));
}
__device__ __forceinline__ void bsplit(float v, __nv_bfloat16& h, __nv_bfloat16& l) {
    h = __float2bfloat16(v);
    l = __float2bfloat16(v - __bfloat162float(h));
}
__device__ __forceinline__ void cpa16(uint32_t saddr, const void* g) {
    asm volatile("cp.async.cg.shared.global [%0], [%1], 16;" :: "r"(saddr), "l"(g));
}
#define CP_COMMIT() asm volatile("cp.async.commit_group;" ::: "memory")
#define CP_WAIT0()  asm volatile("cp.async.wait_group 0;" ::: "memory")
#define CP_WAIT1()  asm volatile("cp.async.wait_group 1;" ::: "memory")

// ---------------------------------------------------------------------------
// prep kernels
// ---------------------------------------------------------------------------
__global__ __launch_bounds__(256) void split_kernel(const float* __restrict__ s,
                                                    __nv_bfloat16* __restrict__ hi,
                                                    __nv_bfloat16* __restrict__ lo)
{
    size_t i = (size_t)blockIdx.x * 1024 + threadIdx.x * 4;
    float4 v = *(const float4*)&s[i];
    float vv[4] = {v.x, v.y, v.z, v.w};
    __nv_bfloat16 h[4], l[4];
    #pragma unroll
    for (int k = 0; k < 4; k++) bsplit(vv[k], h[k], l[k]);
    *(uint2*)&hi[i] = *(uint2*)h;
    *(uint2*)&lo[i] = *(uint2*)l;
}

// W[K][N] -> hi/lo[N][K]
__global__ void wtrans_split(const float* __restrict__ W,
                             __nv_bfloat16* __restrict__ hi,
                             __nv_bfloat16* __restrict__ lo, int K, int N)
{
    __shared__ float t[32][33];
    const int n0 = blockIdx.x * 32, k0 = blockIdx.y * 32;
    const int tx = threadIdx.x, ty = threadIdx.y;  // (32,8)
    for (int i = ty; i < 32; i += 8)
        t[i][tx] = W[(size_t)(k0 + i) * N + n0 + tx];
    __syncthreads();
    for (int i = ty; i < 32; i += 8) {
        float v = t[tx][i];
        __nv_bfloat16 h, l;
        bsplit(v, h, l);
        hi[(size_t)(n0 + i) * K + k0 + tx] = h;
        lo[(size_t)(n0 + i) * K + k0 + tx] = l;
    }
}

// ---------------------------------------------------------------------------
// GEMM: mma.sync + cp.async 2-stage pipeline, BK=32 (small stages -> 2 CTA/SM).
// C[M,N] = A[M,K] @ Bt[N,K]^T ; operands pre-split hi/lo.
// CTA tile 128x128, 8 warps (2m x 4n), warp tile 64x32.
// ---------------------------------------------------------------------------
#define LDK 40                          // padded stride for 32-wide tiles (b16)
#define STG (4 * 128 * LDK)             // elems per stage
#define SMEM_G (2 * STG * 2)            // 81920 B
#define LDT 72                          // padded stride for 64-wide tiles

template<bool SPLIT_OUT>
__global__ __launch_bounds__(256, 2) void gemm_mma(const __nv_bfloat16* __restrict__ ahi,
                                                   const __nv_bfloat16* __restrict__ alo,
                                                   const __nv_bfloat16* __restrict__ bhi,
                                                   const __nv_bfloat16* __restrict__ blo,
                                                   float* __restrict__ Cf,
                                                   __nv_bfloat16* __restrict__ Chi,
                                                   __nv_bfloat16* __restrict__ Clo,
                                                   int N, int K)
{
    extern __shared__ __nv_bfloat16 sm[];

    const int tid = threadIdx.x, lane = tid & 31, wid = tid >> 5;
    const int wm = (wid >> 2) * 64, wn = (wid & 3) * 32;
    const int row0 = blockIdx.y * 128, col0 = blockIdx.x * 128;
    const int lrow = lane & 15;
    const int lcol = (lane >> 4) * 8;

    const uint32_t smb = smem_u32(sm);

    // per-thread load slice: rows tid>>2 and +64, 16B chunk (tid&3)*8
    const int r_ = tid >> 2, cb_ = (tid & 3) * 8;

    auto issue = [&](int ch, int s) {
        const int k0 = ch * 32;
        const uint32_t sb = smb + (uint32_t)s * STG * 2;
        #pragma unroll
        for (int rr = 0; rr < 2; rr++) {
            int r = r_ + rr * 64;
            uint32_t so = (uint32_t)(r * LDK + cb_) * 2;
            size_t ga = (size_t)(row0 + r) * K + k0 + cb_;
            size_t gb = (size_t)(col0 + r) * K + k0 + cb_;
            cpa16(sb + so,               ahi + ga);
            cpa16(sb + 128*LDK*2 + so,   alo + ga);
            cpa16(sb + 2*128*LDK*2 + so, bhi + gb);
            cpa16(sb + 3*128*LDK*2 + so, blo + gb);
        }
        CP_COMMIT();
    };

    float c[4][4][4] = {};
    const int NCH = K / 32;

    issue(0, 0);
    for (int ch = 0; ch < NCH; ch++) {
        if (ch + 1 < NCH) { issue(ch + 1, (ch + 1) & 1); CP_WAIT1(); }
        else              { CP_WAIT0(); }
        __syncthreads();

        const uint32_t sb  = smb + (uint32_t)(ch & 1) * STG * 2;
        const uint32_t sAh = sb;
        const uint32_t sAl = sb + 128*LDK*2;
        const uint32_t sBh = sb + 2*128*LDK*2;
        const uint32_t sBl = sb + 3*128*LDK*2;

        #pragma unroll
        for (int kt = 0; kt < 2; kt++) {
            uint32_t ah[4][4], al[4][4], bh[2][4], bl[2][4];
            #pragma unroll
            for (int mt = 0; mt < 4; mt++) {
                uint32_t off = ((wm + mt * 16 + lrow) * LDK + kt * 16 + lcol) * 2;
                ldsm4(ah[mt], sAh + off);
                ldsm4(al[mt], sAl + off);
            }
            #pragma unroll
            for (int bt = 0; bt < 2; bt++) {
                uint32_t off = ((wn + bt * 16 + lrow) * LDK + kt * 16 + lcol) * 2;
                ldsm4(bh[bt], sBh + off);
                ldsm4(bl[bt], sBl + off);
            }
            #pragma unroll
            for (int mt = 0; mt < 4; mt++)
                #pragma unroll
                for (int nt = 0; nt < 4; nt++) {
                    const int bt = nt >> 1, s = nt & 1;
                    mma16816(c[mt][nt], ah[mt], bh[bt][s], bh[bt][s + 2]);
                    mma16816(c[mt][nt], al[mt], bh[bt][s], bh[bt][s + 2]);
                    mma16816(c[mt][nt], ah[mt], bl[bt][s], bl[bt][s + 2]);
                }
        }
        __syncthreads();
    }

    const int g = lane >> 2, tg = lane & 3;
    #pragma unroll
    for (int mt = 0; mt < 4; mt++)
        #pragma unroll
        for (int nt = 0; nt < 4; nt++) {
            const int row = row0 + wm + mt * 16 + g;
            const int col = col0 + wn + nt * 8 + tg * 2;
            if (SPLIT_OUT) {
                __nv_bfloat16 h0, l0, h1, l1;
                bsplit(c[mt][nt][0], h0, l0);
                bsplit(c[mt][nt][1], h1, l1);
                __nv_bfloat162 hh; hh.x = h0; hh.y = h1;
                __nv_bfloat162 ll; ll.x = l0; ll.y = l1;
                *(__nv_bfloat162*)(Chi + (size_t)row * N + col) = hh;
                *(__nv_bfloat162*)(Clo + (size_t)row * N + col) = ll;
                bsplit(c[mt][nt][2], h0, l0);
                bsplit(c[mt][nt][3], h1, l1);
                hh.x = h0; hh.y = h1; ll.x = l0; ll.y = l1;
                *(__nv_bfloat162*)(Chi + (size_t)(row + 8) * N + col) = hh;
                *(__nv_bfloat162*)(Clo + (size_t)(row + 8) * N + col) = ll;
            } else {
                *(float2*)(Cf + (size_t)row * N + col) = make_float2(c[mt][nt][0], c[mt][nt][1]);
                *(float2*)(Cf + (size_t)(row + 8) * N + col) = make_float2(c[mt][nt][2], c[mt][nt][3]);
            }
        }
}

// ---------------------------------------------------------------------------
// Scores: S = (Q.K^T)/8 for lower-triangular 128x128 tile pairs. K-dim = 64.
// ---------------------------------------------------------------------------
#define SMEM_S (4 * 128 * LDT * 2)

__global__ __launch_bounds__(256, 2) void scores_mma(const __nv_bfloat16* __restrict__ qh,
                                                     const __nv_bfloat16* __restrict__ ql,
                                                     float* __restrict__ attn)
{
    const int t = blockIdx.x, h = blockIdx.y, b = blockIdx.z;
    int i = 0;
    while ((i + 1) * (i + 2) / 2 <= t) i++;
    const int j = t - i * (i + 1) / 2;

    extern __shared__ __nv_bfloat16 sm[];
    const uint32_t smb = smem_u32(sm);
    const uint32_t sQh = smb;
    const uint32_t sQl = smb + 128*LDT*2;
    const uint32_t sKh = smb + 2*128*LDT*2;
    const uint32_t sKl = smb + 3*128*LDT*2;

    const int tid = threadIdx.x, lane = tid & 31, wid = tid >> 5;
    const int wm = (wid >> 2) * 64, wn = (wid & 3) * 32;
    const int lrow = lane & 15, lcol = (lane >> 4) * 8;

    {
        const int r_ = tid >> 3, cb_ = (tid & 7) * 8;
        #pragma unroll
        for (int rr = 0; rr < 4; rr++) {
            int r = r_ + rr * 32;
            uint32_t so = (uint32_t)(r * LDT + cb_) * 2;
            size_t qa = (size_t)(b * N_SEQ + i * 128 + r) * QKV_COLS + h * 64 + cb_;
            size_t ka = (size_t)(b * N_SEQ + j * 128 + r) * QKV_COLS + D_MODEL + h * 64 + cb_;
            cpa16(sQh + so, qh + qa);
            cpa16(sQl + so, ql + qa);
            cpa16(sKh + so, qh + ka);
            cpa16(sKl + so, ql + ka);
        }
        CP_COMMIT();
        CP_WAIT0();
    }
    __syncthreads();

    float c[4][4][4] = {};
    #pragma unroll
    for (int kt = 0; kt < 4; kt++) {
        uint32_t ah[4][4], al[4][4], bh[2][4], bl[2][4];
        #pragma unroll
        for (int mt = 0; mt < 4; mt++) {
            uint32_t off = ((wm + mt * 16 + lrow) * LDT + kt * 16 + lcol) * 2;
            ldsm4(ah[mt], sQh + off);
            ldsm4(al[mt], sQl + off);
        }
        #pragma unroll
        for (int bt = 0; bt < 2; bt++) {
            uint32_t off = ((wn + bt * 16 + lrow) * LDT + kt * 16 + lcol) * 2;
            ldsm4(bh[bt], sKh + off);
            ldsm4(bl[bt], sKl + off);
        }
        #pragma unroll
        for (int mt = 0; mt < 4; mt++)
            #pragma unroll
            for (int nt = 0; nt < 4; nt++) {
                const int bt = nt >> 1, s = nt & 1;
                mma16816(c[mt][nt], ah[mt], bh[bt][s], bh[bt][s + 2]);
                mma16816(c[mt][nt], al[mt], bh[bt][s], bh[bt][s + 2]);
                mma16816(c[mt][nt], ah[mt], bl[bt][s], bl[bt][s + 2]);
            }
    }

    float* base = attn + ((size_t)(b * N_HEADS + h)) * N_SEQ * N_SEQ;
    const int g = lane >> 2, tg = lane & 3;
    #pragma unroll
    for (int mt = 0; mt < 4; mt++)
        #pragma unroll
        for (int nt = 0; nt < 4; nt++) {
            const int q = i * 128 + wm + mt * 16 + g;
            const int col = j * 128 + wn + nt * 8 + tg * 2;
            *(float2*)(base + (size_t)q * N_SEQ + col) =
                make_float2(c[mt][nt][0] * 0.125f, c[mt][nt][1] * 0.125f);
            *(float2*)(base + (size_t)(q + 8) * N_SEQ + col) =
                make_float2(c[mt][nt][2] * 0.125f, c[mt][nt][3] * 0.125f);
        }
}

// ---------------------------------------------------------------------------
// Row softmax over causal prefix; store-once epilogue (also zero-fills).
// ---------------------------------------------------------------------------
__global__ __launch_bounds__(256) void normalize_kernel(float* __restrict__ attn)
{
    const int n = blockIdx.x, h = blockIdx.y, b = blockIdx.z;
    const int tid = threadIdx.x;

    float* row = attn + (((size_t)(b * N_HEADS + h) * N_SEQ + n)) * N_SEQ;
    __shared__ float red[256];

    const int P = n + 1;
    const int n4full = P >> 2;
    const int tail = P & 3;

    float lmax = -INFINITY;
    for (int m4 = tid; m4 < n4full; m4 += 256) {
        float4 v = *(const float4*)&row[m4 * 4];
        lmax = fmaxf(lmax, fmaxf(fmaxf(v.x, v.y), fmaxf(v.z, v.w)));
    }
    if (tid < tail) lmax = fmaxf(lmax, row[n4full * 4 + tid]);
    red[tid] = lmax;
    __syncthreads();
    #pragma unroll
    for (int s = 128; s > 0; s >>= 1) {
        if (tid < s) red[tid] = fmaxf(red[tid], red[tid + s]);
        __syncthreads();
    }
    const float mx = red[0];
    __syncthreads();

    float lsum = 0.f;
    for (int m4 = tid; m4 < n4full; m4 += 256) {
        float4 v = *(const float4*)&row[m4 * 4];
        lsum += __expf(v.x - mx) + __expf(v.y - mx) + __expf(v.z - mx) + __expf(v.w - mx);
    }
    if (tid < tail) lsum += __expf(row[n4full * 4 + tid] - mx);
    red[tid] = lsum;
    __syncthreads();
    #pragma unroll
    for (int s = 128; s > 0; s >>= 1) {
        if (tid < s) red[tid] += red[tid + s];
        __syncthreads();
    }
    const float inv = 1.f / red[0];
    __syncthreads();

    for (int m4 = tid; m4 < N_SEQ / 4; m4 += 256) {
        float4 o;
        if (m4 < n4full) {
            float4 v = *(const float4*)&row[m4 * 4];
            o.x = __expf(v.x - mx) * inv;
            o.y = __expf(v.y - mx) * inv;
            o.z = __expf(v.z - mx) * inv;
            o.w = __expf(v.w - mx) * inv;
        } else if (m4 == n4full && tail) {
            float4 v = *(const float4*)&row[m4 * 4];
            float vv[4] = {v.x, v.y, v.z, v.w};
            float oo[4];
            #pragma unroll
            for (int k = 0; k < 4; k++)
                oo[k] = (m4 * 4 + k < P) ? __expf(vv[k] - mx) * inv : 0.f;
            o = make_float4(oo[0], oo[1], oo[2], oo[3]);
        } else {
            o = make_float4(0.f, 0.f, 0.f, 0.f);
        }
        *(float4*)&row[m4 * 4] = o;
    }
}

// ---------------------------------------------------------------------------
// PV: ctx = P @ V over causal 128-key tiles, mma.sync, split P in smem.
// ---------------------------------------------------------------------------
#define LDP 136
#define SMEM_PV ((2 * 128 * LDP + 2 * 128 * LDT) * 2)   // 106496 B

__global__ __launch_bounds__(256, 2) void pv_mma(const float* __restrict__ attn,
                                                 const __nv_bfloat16* __restrict__ qh,
                                                 const __nv_bfloat16* __restrict__ ql,
                                                 __nv_bfloat16* __restrict__ ch,
                                                 __nv_bfloat16* __restrict__ cl)
{
    const int i = blockIdx.x, h = blockIdx.y, b = blockIdx.z;

    extern __shared__ __nv_bfloat16 sm[];
    __nv_bfloat16* Ph = sm;
    __nv_bfloat16* Pl = Ph + 128 * LDP;
    __nv_bfloat16* Vh = Pl + 128 * LDP;
    __nv_bfloat16* Vl = Vh + 128 * LDT;

    const int tid = threadIdx.x, lane = tid & 31, wid = tid >> 5;
    const int wm = (wid >> 1) * 32, wn = (wid & 1) * 32;
    const int lrow = lane & 15, lcol = (lane >> 4) * 8;

    const uint32_t sPh = smem_u32(Ph), sPl = smem_u32(Pl);
    const uint32_t sVh = smem_u32(Vh), sVl = smem_u32(Vl);

    const float* base = attn + ((size_t)(b * N_HEADS + h)) * N_SEQ * N_SEQ
                             + (size_t)i * 128 * N_SEQ;
    float c[2][4][4] = {};

    for (int j = 0; j <= i; j++) {
        if (j) __syncthreads();
        // V tile via cp.async (overlaps with the P convert below)
        {
            const int r_ = tid >> 3, cb_ = (tid & 7) * 8;
            #pragma unroll
            for (int rr = 0; rr < 4; rr++) {
                int r = r_ + rr * 32;
                uint32_t so = (uint32_t)(r * LDT + cb_) * 2;
                size_t va = (size_t)(b * N_SEQ + j * 128 + r) * QKV_COLS + 2 * D_MODEL + h * 64 + cb_;
                cpa16(sVh + so, qh + va);
                cpa16(sVl + so, ql + va);
            }
            CP_COMMIT();
        }
        // P tile 128x128 fp32 -> split hi/lo bf16 in smem
        for (int e = tid; e < 4096; e += 256) {
            int r = e >> 5, c4 = (e & 31) * 4;
            float4 v = *(const float4*)(base + (size_t)r * N_SEQ + j * 128 + c4);
            float vv[4] = {v.x, v.y, v.z, v.w};
            __nv_bfloat16 hh[4], ll[4];
            #pragma unroll
            for (int k = 0; k < 4; k++) bsplit(vv[k], hh[k], ll[k]);
            *(uint2*)(Ph + r * LDP + c4) = *(uint2*)hh;
            *(uint2*)(Pl + r * LDP + c4) = *(uint2*)ll;
        }
        CP_WAIT0();
        __syncthreads();

        #pragma unroll
        for (int kt = 0; kt < 8; kt++) {
            uint32_t ah[2][4], al[2][4], vh[2][4], vl[2][4];
            #pragma unroll
            for (int mt = 0; mt < 2; mt++) {
                uint32_t off = ((wm + mt * 16 + lrow) * LDP + kt * 16 + lcol) * 2;
                ldsm4(ah[mt], sPh + off);
                ldsm4(al[mt], sPl + off);
            }
            #pragma unroll
            for (int bt = 0; bt < 2; bt++) {
                uint32_t off = ((kt * 16 + lrow) * LDT + wn + bt * 16 + lcol) * 2;
                ldsm4t(vh[bt], sVh + off);
                ldsm4t(vl[bt], sVl + off);
            }
            #pragma unroll
            for (int mt = 0; mt < 2; mt++)
                #pragma unroll
                for (int nt = 0; nt < 4; nt++) {
                    const int bt = nt >> 1, s = (nt & 1) * 2;
                    mma16816(c[mt][nt], ah[mt], vh[bt][s], vh[bt][s + 1]);
                    mma16816(c[mt][nt], al[mt], vh[bt][s], vh[bt][s + 1]);
                    mma16816(c[mt][nt], ah[mt], vl[bt][s], vl[bt][s + 1]);
                }
        }
    }

    const int g = lane >> 2, tg = lane & 3;
    #pragma unroll
    for (int mt = 0; mt < 2; mt++)
        #pragma unroll
        for (int nt = 0; nt < 4; nt++) {
            const int q = i * 128 + wm + mt * 16 + g;
            const int d = wn + nt * 8 + tg * 2;
            __nv_bfloat16 h0, l0, h1, l1;
            bsplit(c[mt][nt][0], h0, l0);
            bsplit(c[mt][nt][1], h1, l1);
            __nv_bfloat162 hh; hh.x = h0; hh.y = h1;
            __nv_bfloat162 ll; ll.x = l0; ll.y = l1;
            *(__nv_bfloat162*)(ch + (size_t)(b * N_SEQ + q) * D_MODEL + h * 64 + d) = hh;
            *(__nv_bfloat162*)(cl + (size_t)(b * N_SEQ + q) * D_MODEL + h * 64 + d) = ll;
            bsplit(c[mt][nt][2], h0, l0);
            bsplit(c[mt][nt][3], h1, l1);
            hh.x = h0; hh.y = h1; ll.x = l0; ll.y = l1;
            *(__nv_bfloat162*)(ch + (size_t)(b * N_SEQ + q + 8) * D_MODEL + h * 64 + d) = hh;
            *(__nv_bfloat162*)(cl + (size_t)(b * N_SEQ + q + 8) * D_MODEL + h * 64 + d) = ll;
        }
}

// ---------------------------------------------------------------------------
extern "C" void kernel_launch(void* const* d_in, const int* in_sizes, int n_in,
                              void* d_out, int out_size)
{
    const float* x     = (const float*)d_in[0];
    const float* W_qkv = (const float*)d_in[1];
    const float* W_out = (const float*)d_in[2];
    float* out = (float*)d_out;

    float* attn_scratch;
    __nv_bfloat16 *xh, *xl, *qkvh, *qkvl, *ch, *cl, *wqh, *wql, *woh, *wol;
    cudaGetSymbolAddress((void**)&attn_scratch, g_attn);
    cudaGetSymbolAddress((void**)&xh, g_xh);
    cudaGetSymbolAddress((void**)&xl, g_xl);
    cudaGetSymbolAddress((void**)&qkvh, g_qkvh);
    cudaGetSymbolAddress((void**)&qkvl, g_qkvl);
    cudaGetSymbolAddress((void**)&ch, g_ch);
    cudaGetSymbolAddress((void**)&cl, g_cl);
    cudaGetSymbolAddress((void**)&wqh, g_wqh);
    cudaGetSymbolAddress((void**)&wql, g_wql);
    cudaGetSymbolAddress((void**)&woh, g_woh);
    cudaGetSymbolAddress((void**)&wol, g_wol);

    cudaFuncSetAttribute(gemm_mma<true>,  cudaFuncAttributeMaxDynamicSharedMemorySize, SMEM_G);
    cudaFuncSetAttribute(gemm_mma<false>, cudaFuncAttributeMaxDynamicSharedMemorySize, SMEM_G);
    cudaFuncSetAttribute(scores_mma,      cudaFuncAttributeMaxDynamicSharedMemorySize, SMEM_S);
    cudaFuncSetAttribute(pv_mma,          cudaFuncAttributeMaxDynamicSharedMemorySize, SMEM_PV);

    const long long out_elems  = (long long)B_SZ * N_SEQ * D_MODEL;
    const long long attn_elems = (long long)B_SZ * N_HEADS * N_SEQ * N_SEQ;
    const int write_attn = ((long long)out_size >= out_elems + attn_elems) ? 1 : 0;
    float* attn_buf = write_attn ? (out + out_elems) : attn_scratch;

    // 0) prep
    split_kernel<<<(M_ROWS * D_MODEL) / 1024, 256>>>(x, xh, xl);
    {
        dim3 grid(QKV_COLS / 32, D_MODEL / 32);
        wtrans_split<<<grid, dim3(32, 8)>>>(W_qkv, wqh, wql, D_MODEL, QKV_COLS);
    }
    {
        dim3 grid(D_MODEL / 32, D_MODEL / 32);
        wtrans_split<<<grid, dim3(32, 8)>>>(W_out, woh, wol, D_MODEL, D_MODEL);
    }

    // 1) QKV projection -> split bf16 qkv
    {
        dim3 grid(QKV_COLS / 128, M_ROWS / 128);
        gemm_mma<true><<<grid, 256, SMEM_G>>>(xh, xl, wqh, wql,
                                              nullptr, qkvh, qkvl, QKV_COLS, D_MODEL);
    }
    // 2a) scores
    {
        dim3 grid(NPAIR128, N_HEADS, B_SZ);
        scores_mma<<<grid, 256, SMEM_S>>>(qkvh, qkvl, attn_buf);
    }
    // 2b) softmax
    {
        dim3 grid(N_SEQ, N_HEADS, B_SZ);
        normalize_kernel<<<grid, 256>>>(attn_buf);
    }
    // 2c) P @ V -> split bf16 ctx
    {
        dim3 grid(NT128, N_HEADS, B_SZ);
        pv_mma<<<grid, 256, SMEM_PV>>>(attn_buf, qkvh, qkvl, ch, cl);
    }
    // 3) output projection -> fp32 out
    {
        dim3 grid(D_MODEL / 128, M_ROWS / 128);
        gemm_mma<false><<<grid, 256, SMEM_G>>>(ch, cl, woh, wol,
                                               out, nullptr, nullptr, D_MODEL, D_MODEL);
    }
}

// round 10
// speedup vs baseline: 1.3319x; 1.3319x over previous
#include <cuda_runtime.h>
#include <cuda_bf16.h>
#include <math.h>
#include <stdint.h>

#define B_SZ    2
#define N_SEQ   2048
#define D_MODEL 1024
#define N_HEADS 16
#define D_HEAD  64
#define M_ROWS  (B_SZ * N_SEQ)        // 4096
#define QKV_COLS (3 * D_MODEL)        // 3072
#define NT128   (N_SEQ / 128)         // 16
#define NPAIR128 (NT128 * (NT128 + 1) / 2)  // 136

// ---------------- scratch ---------------------------------------------------
__device__ float g_attn[(size_t)B_SZ * N_HEADS * N_SEQ * N_SEQ];      // fallback
__device__ float2 g_stats[(size_t)B_SZ * N_HEADS * N_SEQ];
__device__ __nv_bfloat16 g_xh[(size_t)M_ROWS * D_MODEL];
__device__ __nv_bfloat16 g_xl[(size_t)M_ROWS * D_MODEL];
__device__ __nv_bfloat16 g_qkvh[(size_t)M_ROWS * QKV_COLS];
__device__ __nv_bfloat16 g_qkvl[(size_t)M_ROWS * QKV_COLS];
__device__ __nv_bfloat16 g_ch[(size_t)M_ROWS * D_MODEL];
__device__ __nv_bfloat16 g_cl[(size_t)M_ROWS * D_MODEL];
__device__ __nv_bfloat16 g_wqh[(size_t)QKV_COLS * D_MODEL];   // [N][K]
__device__ __nv_bfloat16 g_wql[(size_t)QKV_COLS * D_MODEL];
__device__ __nv_bfloat16 g_woh[(size_t)D_MODEL * D_MODEL];
__device__ __nv_bfloat16 g_wol[(size_t)D_MODEL * D_MODEL];

// ---------------- helpers ----------------------------------------------------
__device__ __forceinline__ uint32_t smem_u32(const void* p) {
    uint32_t a;
    asm("{ .reg .u64 t; cvta.to.shared.u64 t, %1; cvt.u32.u64 %0, t; }" : "=r"(a) : "l"(p));
    return a;
}
__device__ __forceinline__ void ldsm4(uint32_t* r, uint32_t a) {
    asm volatile("ldmatrix.sync.aligned.m8n8.x4.shared.b16 {%0,%1,%2,%3}, [%4];"
                 : "=r"(r[0]), "=r"(r[1]), "=r"(r[2]), "=r"(r[3]) : "r"(a));
}
__device__ __forceinline__ void ldsm4t(uint32_t* r, uint32_t a) {
    asm volatile("ldmatrix.sync.aligned.m8n8.x4.trans.shared.b16 {%0,%1,%2,%3}, [%4];"
                 : "=r"(r[0]), "=r"(r[1]), "=r"(r[2]), "=r"(r[3]) : "r"(a));
}
__device__ __forceinline__ void mma16816(float* c, const uint32_t* a, uint32_t b0, uint32_t b1) {
    asm volatile("mma.sync.aligned.m16n8k16.row.col.f32.bf16.bf16.f32 "
                 "{%0,%1,%2,%3}, {%4,%5,%6,%7}, {%8,%9}, {%0,%1,%2,%3};"
                 : "+f"(c[0]), "+f"(c[1]), "+f"(c[2]), "+f"(c[3])
                 : "r"(a[0]), "r"(a[1]), "r"(a[2]), "r"(a[3]), "r"(b0), "r"(b1));
}
__device__ __forceinline__ void bsplit(float v, __nv_bfloat16& h, __nv_bfloat16& l) {
    h = __float2bfloat16(v);
    l = __float2bfloat16(v - __bfloat162float(h));
}
__device__ __forceinline__ void cpa16(uint32_t saddr, const void* g) {
    asm volatile("cp.async.cg.shared.global [%0], [%1], 16;" :: "r"(saddr), "l"(g));
}
#define CP_COMMIT() asm volatile("cp.async.commit_group;" ::: "memory")
#define CP_WAIT0()  asm volatile("cp.async.wait_group 0;" ::: "memory")

// ---------------------------------------------------------------------------
// prep kernels
// ---------------------------------------------------------------------------
__global__ __launch_bounds__(256) void split_kernel(const float* __restrict__ s,
                                                    __nv_bfloat16* __restrict__ hi,
                                                    __nv_bfloat16* __restrict__ lo)
{
    size_t i = (size_t)blockIdx.x * 1024 + threadIdx.x * 4;
    float4 v = *(const float4*)&s[i];
    float vv[4] = {v.x, v.y, v.z, v.w};
    __nv_bfloat16 h[4], l[4];
    #pragma unroll
    for (int k = 0; k < 4; k++) bsplit(vv[k], h[k], l[k]);
    *(uint2*)&hi[i] = *(uint2*)h;
    *(uint2*)&lo[i] = *(uint2*)l;
}

// W[K][N] -> hi/lo[N][K]
__global__ void wtrans_split(const float* __restrict__ W,
                             __nv_bfloat16* __restrict__ hi,
                             __nv_bfloat16* __restrict__ lo, int K, int N)
{
    __shared__ float t[32][33];
    const int n0 = blockIdx.x * 32, k0 = blockIdx.y * 32;
    const int tx = threadIdx.x, ty = threadIdx.y;  // (32,8)
    for (int i = ty; i < 32; i += 8)
        t[i][tx] = W[(size_t)(k0 + i) * N + n0 + tx];
    __syncthreads();
    for (int i = ty; i < 32; i += 8) {
        float v = t[tx][i];
        __nv_bfloat16 h, l;
        bsplit(v, h, l);
        hi[(size_t)(n0 + i) * K + k0 + tx] = h;
        lo[(size_t)(n0 + i) * K + k0 + tx] = l;
    }
}

// ---------------------------------------------------------------------------
// GEMM (Round-5 proven form): mma.sync, single-stage smem, BK=64.
// C[M,N] = A[M,K] @ Bt[N,K]^T ; CTA tile 128x128, 8 warps (2m x 4n).
// ---------------------------------------------------------------------------
#define LDT 72
#define SMEM_G (4 * 128 * LDT * 2)   // 73728 B

template<bool SPLIT_OUT>
__global__ __launch_bounds__(256) void gemm_mma(const __nv_bfloat16* __restrict__ ahi,
                                                const __nv_bfloat16* __restrict__ alo,
                                                const __nv_bfloat16* __restrict__ bhi,
                                                const __nv_bfloat16* __restrict__ blo,
                                                float* __restrict__ Cf,
                                                __nv_bfloat16* __restrict__ Chi,
                                                __nv_bfloat16* __restrict__ Clo,
                                                int N, int K)
{
    extern __shared__ __nv_bfloat16 sm[];
    __nv_bfloat16* Ah = sm;
    __nv_bfloat16* Al = Ah + 128 * LDT;
    __nv_bfloat16* Bh = Al + 128 * LDT;
    __nv_bfloat16* Bl = Bh + 128 * LDT;

    const int tid = threadIdx.x, lane = tid & 31, wid = tid >> 5;
    const int wm = (wid >> 2) * 64, wn = (wid & 3) * 32;
    const int row0 = blockIdx.y * 128, col0 = blockIdx.x * 128;
    const int lrow = lane & 15;
    const int lcol = (lane >> 4) * 8;

    const uint32_t sAh = smem_u32(Ah), sAl = smem_u32(Al);
    const uint32_t sBh = smem_u32(Bh), sBl = smem_u32(Bl);

    float c[4][4][4] = {};

    for (int k0 = 0; k0 < K; k0 += 64) {
        for (int e = tid; e < 1024; e += 256) {
            int r = e >> 3, cb = (e & 7) * 8;
            size_t ga = (size_t)(row0 + r) * K + k0 + cb;
            size_t gb = (size_t)(col0 + r) * K + k0 + cb;
            *(uint4*)(Ah + r * LDT + cb) = *(const uint4*)(ahi + ga);
            *(uint4*)(Al + r * LDT + cb) = *(const uint4*)(alo + ga);
            *(uint4*)(Bh + r * LDT + cb) = *(const uint4*)(bhi + gb);
            *(uint4*)(Bl + r * LDT + cb) = *(const uint4*)(blo + gb);
        }
        __syncthreads();

        #pragma unroll
        for (int kt = 0; kt < 4; kt++) {
            uint32_t ah[4][4], al[4][4], bh[2][4], bl[2][4];
            #pragma unroll
            for (int mt = 0; mt < 4; mt++) {
                uint32_t off = ((wm + mt * 16 + lrow) * LDT + kt * 16 + lcol) * 2;
                ldsm4(ah[mt], sAh + off);
                ldsm4(al[mt], sAl + off);
            }
            #pragma unroll
            for (int bt = 0; bt < 2; bt++) {
                uint32_t off = ((wn + bt * 16 + lrow) * LDT + kt * 16 + lcol) * 2;
                ldsm4(bh[bt], sBh + off);
                ldsm4(bl[bt], sBl + off);
            }
            #pragma unroll
            for (int mt = 0; mt < 4; mt++)
                #pragma unroll
                for (int nt = 0; nt < 4; nt++) {
                    const int bt = nt >> 1, s = nt & 1;
                    mma16816(c[mt][nt], ah[mt], bh[bt][s], bh[bt][s + 2]);
                    mma16816(c[mt][nt], al[mt], bh[bt][s], bh[bt][s + 2]);
                    mma16816(c[mt][nt], ah[mt], bl[bt][s], bl[bt][s + 2]);
                }
        }
        __syncthreads();
    }

    const int g = lane >> 2, tg = lane & 3;
    #pragma unroll
    for (int mt = 0; mt < 4; mt++)
        #pragma unroll
        for (int nt = 0; nt < 4; nt++) {
            const int row = row0 + wm + mt * 16 + g;
            const int col = col0 + wn + nt * 8 + tg * 2;
            if (SPLIT_OUT) {
                __nv_bfloat16 h0, l0, h1, l1;
                bsplit(c[mt][nt][0], h0, l0);
                bsplit(c[mt][nt][1], h1, l1);
                __nv_bfloat162 hh; hh.x = h0; hh.y = h1;
                __nv_bfloat162 ll; ll.x = l0; ll.y = l1;
                *(__nv_bfloat162*)(Chi + (size_t)row * N + col) = hh;
                *(__nv_bfloat162*)(Clo + (size_t)row * N + col) = ll;
                bsplit(c[mt][nt][2], h0, l0);
                bsplit(c[mt][nt][3], h1, l1);
                hh.x = h0; hh.y = h1; ll.x = l0; ll.y = l1;
                *(__nv_bfloat162*)(Chi + (size_t)(row + 8) * N + col) = hh;
                *(__nv_bfloat162*)(Clo + (size_t)(row + 8) * N + col) = ll;
            } else {
                *(float2*)(Cf + (size_t)row * N + col) = make_float2(c[mt][nt][0], c[mt][nt][1]);
                *(float2*)(Cf + (size_t)(row + 8) * N + col) = make_float2(c[mt][nt][2], c[mt][nt][3]);
            }
        }
}

// ---------------------------------------------------------------------------
// Scores: S = (Q.K^T)/8 for lower-triangular 128x128 tile pairs. K-dim = 64.
// ---------------------------------------------------------------------------
#define SMEM_S (4 * 128 * LDT * 2)

__global__ __launch_bounds__(256, 2) void scores_mma(const __nv_bfloat16* __restrict__ qh,
                                                     const __nv_bfloat16* __restrict__ ql,
                                                     float* __restrict__ attn)
{
    const int t = blockIdx.x, h = blockIdx.y, b = blockIdx.z;
    int i = 0;
    while ((i + 1) * (i + 2) / 2 <= t) i++;
    const int j = t - i * (i + 1) / 2;

    extern __shared__ __nv_bfloat16 sm[];
    const uint32_t smb = smem_u32(sm);
    const uint32_t sQh = smb;
    const uint32_t sQl = smb + 128*LDT*2;
    const uint32_t sKh = smb + 2*128*LDT*2;
    const uint32_t sKl = smb + 3*128*LDT*2;

    const int tid = threadIdx.x, lane = tid & 31, wid = tid >> 5;
    const int wm = (wid >> 2) * 64, wn = (wid & 3) * 32;
    const int lrow = lane & 15, lcol = (lane >> 4) * 8;

    {
        const int r_ = tid >> 3, cb_ = (tid & 7) * 8;
        #pragma unroll
        for (int rr = 0; rr < 4; rr++) {
            int r = r_ + rr * 32;
            uint32_t so = (uint32_t)(r * LDT + cb_) * 2;
            size_t qa = (size_t)(b * N_SEQ + i * 128 + r) * QKV_COLS + h * 64 + cb_;
            size_t ka = (size_t)(b * N_SEQ + j * 128 + r) * QKV_COLS + D_MODEL + h * 64 + cb_;
            cpa16(sQh + so, qh + qa);
            cpa16(sQl + so, ql + qa);
            cpa16(sKh + so, qh + ka);
            cpa16(sKl + so, ql + ka);
        }
        CP_COMMIT();
        CP_WAIT0();
    }
    __syncthreads();

    float c[4][4][4] = {};
    #pragma unroll
    for (int kt = 0; kt < 4; kt++) {
        uint32_t ah[4][4], al[4][4], bh[2][4], bl[2][4];
        #pragma unroll
        for (int mt = 0; mt < 4; mt++) {
            uint32_t off = ((wm + mt * 16 + lrow) * LDT + kt * 16 + lcol) * 2;
            ldsm4(ah[mt], sQh + off);
            ldsm4(al[mt], sQl + off);
        }
        #pragma unroll
        for (int bt = 0; bt < 2; bt++) {
            uint32_t off = ((wn + bt * 16 + lrow) * LDT + kt * 16 + lcol) * 2;
            ldsm4(bh[bt], sKh + off);
            ldsm4(bl[bt], sKl + off);
        }
        #pragma unroll
        for (int mt = 0; mt < 4; mt++)
            #pragma unroll
            for (int nt = 0; nt < 4; nt++) {
                const int bt = nt >> 1, s = nt & 1;
                mma16816(c[mt][nt], ah[mt], bh[bt][s], bh[bt][s + 2]);
                mma16816(c[mt][nt], al[mt], bh[bt][s], bh[bt][s + 2]);
                mma16816(c[mt][nt], ah[mt], bl[bt][s], bl[bt][s + 2]);
            }
    }

    float* base = attn + ((size_t)(b * N_HEADS + h)) * N_SEQ * N_SEQ;
    const int g = lane >> 2, tg = lane & 3;
    #pragma unroll
    for (int mt = 0; mt < 4; mt++)
        #pragma unroll
        for (int nt = 0; nt < 4; nt++) {
            const int q = i * 128 + wm + mt * 16 + g;
            const int col = j * 128 + wn + nt * 8 + tg * 2;
            *(float2*)(base + (size_t)q * N_SEQ + col) =
                make_float2(c[mt][nt][0] * 0.125f, c[mt][nt][1] * 0.125f);
            *(float2*)(base + (size_t)(q + 8) * N_SEQ + col) =
                make_float2(c[mt][nt][2] * 0.125f, c[mt][nt][3] * 0.125f);
        }
}

// ---------------------------------------------------------------------------
// Stats: one pass per row -> (max, 1/sum). Values held in registers.
// ---------------------------------------------------------------------------
__global__ __launch_bounds__(256) void stats_kernel(const float* __restrict__ attn,
                                                    float2* __restrict__ stats)
{
    const int n = blockIdx.x, h = blockIdx.y, b = blockIdx.z;
    const int tid = threadIdx.x;
    const float* row = attn + ((size_t)(b * N_HEADS + h) * N_SEQ + n) * N_SEQ;

    __shared__ float red[256];
    const int P = n + 1, n4 = P >> 2, tail = P & 3;

    float v[8];
    int cnt = 0;
    float lmax = -INFINITY;
    for (int c4 = tid; c4 < n4; c4 += 256) {
        float4 x = *(const float4*)&row[c4 * 4];
        v[cnt++] = x.x; v[cnt++] = x.y; v[cnt++] = x.z; v[cnt++] = x.w;
        lmax = fmaxf(lmax, fmaxf(fmaxf(x.x, x.y), fmaxf(x.z, x.w)));
    }
    float tv = 0.f;
    const bool hasT = (tid < tail);
    if (hasT) { tv = row[n4 * 4 + tid]; lmax = fmaxf(lmax, tv); }

    red[tid] = lmax;
    __syncthreads();
    #pragma unroll
    for (int s = 128; s > 0; s >>= 1) {
        if (tid < s) red[tid] = fmaxf(red[tid], red[tid + s]);
        __syncthreads();
    }
    const float mx = red[0];
    __syncthreads();

    float ls = 0.f;
    for (int k = 0; k < cnt; k++) ls += __expf(v[k] - mx);
    if (hasT) ls += __expf(tv - mx);
    red[tid] = ls;
    __syncthreads();
    #pragma unroll
    for (int s = 128; s > 0; s >>= 1) {
        if (tid < s) red[tid] += red[tid + s];
        __syncthreads();
    }
    if (tid == 0)
        stats[(size_t)(b * N_HEADS + h) * N_SEQ + n] = make_float2(mx, 1.f / red[0]);
}

// ---------------------------------------------------------------------------
// PV fused: read raw S tiles, normalize with stats, write P (and zero tiles)
// back to attn, and accumulate ctx = P @ V with split-bf16 mma.sync.
// ---------------------------------------------------------------------------
#define LDP 136
#define SMEM_PV (((2 * 128 * LDP + 2 * 128 * LDT) * 2) + 1024)   // 107520 B

__global__ __launch_bounds__(256, 2) void pv_fused(float* __restrict__ attn,
                                                   const float2* __restrict__ stats,
                                                   const __nv_bfloat16* __restrict__ qh,
                                                   const __nv_bfloat16* __restrict__ ql,
                                                   __nv_bfloat16* __restrict__ ch,
                                                   __nv_bfloat16* __restrict__ cl)
{
    const int i = NT128 - 1 - blockIdx.x;   // heavy blocks first
    const int h = blockIdx.y, b = blockIdx.z;

    extern __shared__ __nv_bfloat16 sm[];
    __nv_bfloat16* Ph = sm;
    __nv_bfloat16* Pl = Ph + 128 * LDP;
    __nv_bfloat16* Vh = Pl + 128 * LDP;
    __nv_bfloat16* Vl = Vh + 128 * LDT;
    float2* st = (float2*)(Vl + 128 * LDT);   // 128 entries

    const int tid = threadIdx.x, lane = tid & 31, wid = tid >> 5;
    const int wm = (wid >> 1) * 32, wn = (wid & 1) * 32;
    const int lrow = lane & 15, lcol = (lane >> 4) * 8;

    const uint32_t sPh = smem_u32(Ph), sPl = smem_u32(Pl);
    const uint32_t sVh = smem_u32(Vh), sVl = smem_u32(Vl);

    if (tid < 128)
        st[tid] = stats[(size_t)(b * N_HEADS + h) * N_SEQ + i * 128 + tid];
    __syncthreads();

    float* base = attn + ((size_t)(b * N_HEADS + h)) * N_SEQ * N_SEQ
                       + (size_t)i * 128 * N_SEQ;

    // zero tiles (future keys): j > i
    for (int j = i + 1; j < NT128; j++) {
        const float4 z = make_float4(0.f, 0.f, 0.f, 0.f);
        for (int e = tid; e < 4096; e += 256) {
            int r = e >> 5, c4 = (e & 31) * 4;
            *(float4*)(base + (size_t)r * N_SEQ + j * 128 + c4) = z;
        }
    }

    float c[2][4][4] = {};

    for (int j = 0; j <= i; j++) {
        if (j) __syncthreads();
        // V tile via cp.async (overlaps with the P normalize/convert below)
        {
            const int r_ = tid >> 3, cb_ = (tid & 7) * 8;
            #pragma unroll
            for (int rr = 0; rr < 4; rr++) {
                int r = r_ + rr * 32;
                uint32_t so = (uint32_t)(r * LDT + cb_) * 2;
                size_t va = (size_t)(b * N_SEQ + j * 128 + r) * QKV_COLS + 2 * D_MODEL + h * 64 + cb_;
                cpa16(sVh + so, qh + va);
                cpa16(sVl + so, ql + va);
            }
            CP_COMMIT();
        }
        // S tile -> P = exp(s - mx) * inv ; diag mask ; write back ; split to smem
        const bool diag = (j == i);
        for (int e = tid; e < 4096; e += 256) {
            int r = e >> 5, c4 = (e & 31) * 4;
            float* gp = base + (size_t)r * N_SEQ + j * 128 + c4;
            float4 v = *(const float4*)gp;
            float2 s2 = st[r];
            float vv[4] = {v.x, v.y, v.z, v.w};
            float pp[4];
            #pragma unroll
            for (int k = 0; k < 4; k++) {
                float p = __expf(vv[k] - s2.x) * s2.y;
                if (diag && (c4 + k > r)) p = 0.f;
                pp[k] = p;
            }
            *(float4*)gp = make_float4(pp[0], pp[1], pp[2], pp[3]);
            __nv_bfloat16 hh[4], ll[4];
            #pragma unroll
            for (int k = 0; k < 4; k++) bsplit(pp[k], hh[k], ll[k]);
            *(uint2*)(Ph + r * LDP + c4) = *(uint2*)hh;
            *(uint2*)(Pl + r * LDP + c4) = *(uint2*)ll;
        }
        CP_WAIT0();
        __syncthreads();

        #pragma unroll
        for (int kt = 0; kt < 8; kt++) {
            uint32_t ah[2][4], al[2][4], vh[2][4], vl[2][4];
            #pragma unroll
            for (int mt = 0; mt < 2; mt++) {
                uint32_t off = ((wm + mt * 16 + lrow) * LDP + kt * 16 + lcol) * 2;
                ldsm4(ah[mt], sPh + off);
                ldsm4(al[mt], sPl + off);
            }
            #pragma unroll
            for (int bt = 0; bt < 2; bt++) {
                uint32_t off = ((kt * 16 + lrow) * LDT + wn + bt * 16 + lcol) * 2;
                ldsm4t(vh[bt], sVh + off);
                ldsm4t(vl[bt], sVl + off);
            }
            #pragma unroll
            for (int mt = 0; mt < 2; mt++)
                #pragma unroll
                for (int nt = 0; nt < 4; nt++) {
                    const int bt = nt >> 1, s = (nt & 1) * 2;
                    mma16816(c[mt][nt], ah[mt], vh[bt][s], vh[bt][s + 1]);
                    mma16816(c[mt][nt], al[mt], vh[bt][s], vh[bt][s + 1]);
                    mma16816(c[mt][nt], ah[mt], vl[bt][s], vl[bt][s + 1]);
                }
        }
    }

    const int g = lane >> 2, tg = lane & 3;
    #pragma unroll
    for (int mt = 0; mt < 2; mt++)
        #pragma unroll
        for (int nt = 0; nt < 4; nt++) {
            const int q = i * 128 + wm + mt * 16 + g;
            const int d = wn + nt * 8 + tg * 2;
            __nv_bfloat16 h0, l0, h1, l1;
            bsplit(c[mt][nt][0], h0, l0);
            bsplit(c[mt][nt][1], h1, l1);
            __nv_bfloat162 hh; hh.x = h0; hh.y = h1;
            __nv_bfloat162 ll; ll.x = l0; ll.y = l1;
            *(__nv_bfloat162*)(ch + (size_t)(b * N_SEQ + q) * D_MODEL + h * 64 + d) = hh;
            *(__nv_bfloat162*)(cl + (size_t)(b * N_SEQ + q) * D_MODEL + h * 64 + d) = ll;
            bsplit(c[mt][nt][2], h0, l0);
            bsplit(c[mt][nt][3], h1, l1);
            hh.x = h0; hh.y = h1; ll.x = l0; ll.y = l1;
            *(__nv_bfloat162*)(ch + (size_t)(b * N_SEQ + q + 8) * D_MODEL + h * 64 + d) = hh;
            *(__nv_bfloat162*)(cl + (size_t)(b * N_SEQ + q + 8) * D_MODEL + h * 64 + d) = ll;
        }
}

// ---------------------------------------------------------------------------
extern "C" void kernel_launch(void* const* d_in, const int* in_sizes, int n_in,
                              void* d_out, int out_size)
{
    const float* x     = (const float*)d_in[0];
    const float* W_qkv = (const float*)d_in[1];
    const float* W_out = (const float*)d_in[2];
    float* out = (float*)d_out;

    float* attn_scratch;
    float2* stats;
    __nv_bfloat16 *xh, *xl, *qkvh, *qkvl, *ch, *cl, *wqh, *wql, *woh, *wol;
    cudaGetSymbolAddress((void**)&attn_scratch, g_attn);
    cudaGetSymbolAddress((void**)&stats, g_stats);
    cudaGetSymbolAddress((void**)&xh, g_xh);
    cudaGetSymbolAddress((void**)&xl, g_xl);
    cudaGetSymbolAddress((void**)&qkvh, g_qkvh);
    cudaGetSymbolAddress((void**)&qkvl, g_qkvl);
    cudaGetSymbolAddress((void**)&ch, g_ch);
    cudaGetSymbolAddress((void**)&cl, g_cl);
    cudaGetSymbolAddress((void**)&wqh, g_wqh);
    cudaGetSymbolAddress((void**)&wql, g_wql);
    cudaGetSymbolAddress((void**)&woh, g_woh);
    cudaGetSymbolAddress((void**)&wol, g_wol);

    cudaFuncSetAttribute(gemm_mma<true>,  cudaFuncAttributeMaxDynamicSharedMemorySize, SMEM_G);
    cudaFuncSetAttribute(gemm_mma<false>, cudaFuncAttributeMaxDynamicSharedMemorySize, SMEM_G);
    cudaFuncSetAttribute(scores_mma,      cudaFuncAttributeMaxDynamicSharedMemorySize, SMEM_S);
    cudaFuncSetAttribute(pv_fused,        cudaFuncAttributeMaxDynamicSharedMemorySize, SMEM_PV);

    const long long out_elems  = (long long)B_SZ * N_SEQ * D_MODEL;
    const long long attn_elems = (long long)B_SZ * N_HEADS * N_SEQ * N_SEQ;
    const int write_attn = ((long long)out_size >= out_elems + attn_elems) ? 1 : 0;
    float* attn_buf = write_attn ? (out + out_elems) : attn_scratch;

    // 0) prep
    split_kernel<<<(M_ROWS * D_MODEL) / 1024, 256>>>(x, xh, xl);
    {
        dim3 grid(QKV_COLS / 32, D_MODEL / 32);
        wtrans_split<<<grid, dim3(32, 8)>>>(W_qkv, wqh, wql, D_MODEL, QKV_COLS);
    }
    {
        dim3 grid(D_MODEL / 32, D_MODEL / 32);
        wtrans_split<<<grid, dim3(32, 8)>>>(W_out, woh, wol, D_MODEL, D_MODEL);
    }

    // 1) QKV projection -> split bf16 qkv
    {
        dim3 grid(QKV_COLS / 128, M_ROWS / 128);
        gemm_mma<true><<<grid, 256, SMEM_G>>>(xh, xl, wqh, wql,
                                              nullptr, qkvh, qkvl, QKV_COLS, D_MODEL);
    }
    // 2a) raw scores
    {
        dim3 grid(NPAIR128, N_HEADS, B_SZ);
        scores_mma<<<grid, 256, SMEM_S>>>(qkvh, qkvl, attn_buf);
    }
    // 2b) per-row softmax stats (single pass)
    {
        dim3 grid(N_SEQ, N_HEADS, B_SZ);
        stats_kernel<<<grid, 256>>>(attn_buf, stats);
    }
    // 2c) fused normalize + P-write + P@V
    {
        dim3 grid(NT128, N_HEADS, B_SZ);
        pv_fused<<<grid, 256, SMEM_PV>>>(attn_buf, stats, qkvh, qkvl, ch, cl);
    }
    // 3) output projection -> fp32 out
    {
        dim3 grid(D_MODEL / 128, M_ROWS / 128);
        gemm_mma<false><<<grid, 256, SMEM_G>>>(ch, cl, woh, wol,
                                               out, nullptr, nullptr, D_MODEL, D_MODEL);
    }
}

// round 11
// speedup vs baseline: 1.5590x; 1.1705x over previous
#include <cuda_runtime.h>
#include <cuda_bf16.h>
#include <math.h>
#include <stdint.h>

#define B_SZ    2
#define N_SEQ   2048
#define D_MODEL 1024
#define N_HEADS 16
#define D_HEAD  64
#define M_ROWS  (B_SZ * N_SEQ)        // 4096
#define QKV_COLS (3 * D_MODEL)        // 3072
#define NT128   (N_SEQ / 128)         // 16
#define NPAIR128 (NT128 * (NT128 + 1) / 2)  // 136

// ---------------- scratch ---------------------------------------------------
__device__ float g_attn[(size_t)B_SZ * N_HEADS * N_SEQ * N_SEQ];      // fallback
__device__ __nv_bfloat16 g_xh[(size_t)M_ROWS * D_MODEL];
__device__ __nv_bfloat16 g_xl[(size_t)M_ROWS * D_MODEL];
__device__ __nv_bfloat16 g_qkvh[(size_t)M_ROWS * QKV_COLS];
__device__ __nv_bfloat16 g_qkvl[(size_t)M_ROWS * QKV_COLS];
__device__ __nv_bfloat16 g_ch[(size_t)M_ROWS * D_MODEL];
__device__ __nv_bfloat16 g_cl[(size_t)M_ROWS * D_MODEL];
__device__ __nv_bfloat16 g_wqh[(size_t)QKV_COLS * D_MODEL];   // [N][K]
__device__ __nv_bfloat16 g_wql[(size_t)QKV_COLS * D_MODEL];
__device__ __nv_bfloat16 g_woh[(size_t)D_MODEL * D_MODEL];
__device__ __nv_bfloat16 g_wol[(size_t)D_MODEL * D_MODEL];

// ---------------- helpers ----------------------------------------------------
__device__ __forceinline__ uint32_t smem_u32(const void* p) {
    uint32_t a;
    asm("{ .reg .u64 t; cvta.to.shared.u64 t, %1; cvt.u32.u64 %0, t; }" : "=r"(a) : "l"(p));
    return a;
}
__device__ __forceinline__ void ldsm4(uint32_t* r, uint32_t a) {
    asm volatile("ldmatrix.sync.aligned.m8n8.x4.shared.b16 {%0,%1,%2,%3}, [%4];"
                 : "=r"(r[0]), "=r"(r[1]), "=r"(r[2]), "=r"(r[3]) : "r"(a));
}
__device__ __forceinline__ void ldsm4t(uint32_t* r, uint32_t a) {
    asm volatile("ldmatrix.sync.aligned.m8n8.x4.trans.shared.b16 {%0,%1,%2,%3}, [%4];"
                 : "=r"(r[0]), "=r"(r[1]), "=r"(r[2]), "=r"(r[3]) : "r"(a));
}
__device__ __forceinline__ void mma16816(float* c, const uint32_t* a, uint32_t b0, uint32_t b1) {
    asm volatile("mma.sync.aligned.m16n8k16.row.col.f32.bf16.bf16.f32 "
                 "{%0,%1,%2,%3}, {%4,%5,%6,%7}, {%8,%9}, {%0,%1,%2,%3};"
                 : "+f"(c[0]), "+f"(c[1]), "+f"(c[2]), "+f"(c[3])
                 : "r"(a[0]), "r"(a[1]), "r"(a[2]), "r"(a[3]), "r"(b0), "r"(b1));
}
__device__ __forceinline__ void bsplit(float v, __nv_bfloat16& h, __nv_bfloat16& l) {
    h = __float2bfloat16(v);
    l = __float2bfloat16(v - __bfloat162float(h));
}
__device__ __forceinline__ void cpa16(uint32_t saddr, const void* g) {
    asm volatile("cp.async.cg.shared.global [%0], [%1], 16;" :: "r"(saddr), "l"(g));
}
#define CP_COMMIT() asm volatile("cp.async.commit_group;" ::: "memory")
#define CP_WAIT0()  asm volatile("cp.async.wait_group 0;" ::: "memory")

// ---------------------------------------------------------------------------
// prep kernels
// ---------------------------------------------------------------------------
__global__ __launch_bounds__(256) void split_kernel(const float* __restrict__ s,
                                                    __nv_bfloat16* __restrict__ hi,
                                                    __nv_bfloat16* __restrict__ lo)
{
    size_t i = (size_t)blockIdx.x * 1024 + threadIdx.x * 4;
    float4 v = *(const float4*)&s[i];
    float vv[4] = {v.x, v.y, v.z, v.w};
    __nv_bfloat16 h[4], l[4];
    #pragma unroll
    for (int k = 0; k < 4; k++) bsplit(vv[k], h[k], l[k]);
    *(uint2*)&hi[i] = *(uint2*)h;
    *(uint2*)&lo[i] = *(uint2*)l;
}

// W[K][N] -> hi/lo[N][K]
__global__ void wtrans_split(const float* __restrict__ W,
                             __nv_bfloat16* __restrict__ hi,
                             __nv_bfloat16* __restrict__ lo, int K, int N)
{
    __shared__ float t[32][33];
    const int n0 = blockIdx.x * 32, k0 = blockIdx.y * 32;
    const int tx = threadIdx.x, ty = threadIdx.y;  // (32,8)
    for (int i = ty; i < 32; i += 8)
        t[i][tx] = W[(size_t)(k0 + i) * N + n0 + tx];
    __syncthreads();
    for (int i = ty; i < 32; i += 8) {
        float v = t[tx][i];
        __nv_bfloat16 h, l;
        bsplit(v, h, l);
        hi[(size_t)(n0 + i) * K + k0 + tx] = h;
        lo[(size_t)(n0 + i) * K + k0 + tx] = l;
    }
}

// ---------------------------------------------------------------------------
// GEMM (Round-5 proven form): mma.sync, single-stage smem, BK=64.
// ---------------------------------------------------------------------------
#define LDT 72
#define SMEM_G (4 * 128 * LDT * 2)   // 73728 B

template<bool SPLIT_OUT>
__global__ __launch_bounds__(256) void gemm_mma(const __nv_bfloat16* __restrict__ ahi,
                                                const __nv_bfloat16* __restrict__ alo,
                                                const __nv_bfloat16* __restrict__ bhi,
                                                const __nv_bfloat16* __restrict__ blo,
                                                float* __restrict__ Cf,
                                                __nv_bfloat16* __restrict__ Chi,
                                                __nv_bfloat16* __restrict__ Clo,
                                                int N, int K)
{
    extern __shared__ __nv_bfloat16 sm[];
    __nv_bfloat16* Ah = sm;
    __nv_bfloat16* Al = Ah + 128 * LDT;
    __nv_bfloat16* Bh = Al + 128 * LDT;
    __nv_bfloat16* Bl = Bh + 128 * LDT;

    const int tid = threadIdx.x, lane = tid & 31, wid = tid >> 5;
    const int wm = (wid >> 2) * 64, wn = (wid & 3) * 32;
    const int row0 = blockIdx.y * 128, col0 = blockIdx.x * 128;
    const int lrow = lane & 15;
    const int lcol = (lane >> 4) * 8;

    const uint32_t sAh = smem_u32(Ah), sAl = smem_u32(Al);
    const uint32_t sBh = smem_u32(Bh), sBl = smem_u32(Bl);

    float c[4][4][4] = {};

    for (int k0 = 0; k0 < K; k0 += 64) {
        for (int e = tid; e < 1024; e += 256) {
            int r = e >> 3, cb = (e & 7) * 8;
            size_t ga = (size_t)(row0 + r) * K + k0 + cb;
            size_t gb = (size_t)(col0 + r) * K + k0 + cb;
            *(uint4*)(Ah + r * LDT + cb) = *(const uint4*)(ahi + ga);
            *(uint4*)(Al + r * LDT + cb) = *(const uint4*)(alo + ga);
            *(uint4*)(Bh + r * LDT + cb) = *(const uint4*)(bhi + gb);
            *(uint4*)(Bl + r * LDT + cb) = *(const uint4*)(blo + gb);
        }
        __syncthreads();

        #pragma unroll
        for (int kt = 0; kt < 4; kt++) {
            uint32_t ah[4][4], al[4][4], bh[2][4], bl[2][4];
            #pragma unroll
            for (int mt = 0; mt < 4; mt++) {
                uint32_t off = ((wm + mt * 16 + lrow) * LDT + kt * 16 + lcol) * 2;
                ldsm4(ah[mt], sAh + off);
                ldsm4(al[mt], sAl + off);
            }
            #pragma unroll
            for (int bt = 0; bt < 2; bt++) {
                uint32_t off = ((wn + bt * 16 + lrow) * LDT + kt * 16 + lcol) * 2;
                ldsm4(bh[bt], sBh + off);
                ldsm4(bl[bt], sBl + off);
            }
            #pragma unroll
            for (int mt = 0; mt < 4; mt++)
                #pragma unroll
                for (int nt = 0; nt < 4; nt++) {
                    const int bt = nt >> 1, s = nt & 1;
                    mma16816(c[mt][nt], ah[mt], bh[bt][s], bh[bt][s + 2]);
                    mma16816(c[mt][nt], al[mt], bh[bt][s], bh[bt][s + 2]);
                    mma16816(c[mt][nt], ah[mt], bl[bt][s], bl[bt][s + 2]);
                }
        }
        __syncthreads();
    }

    const int g = lane >> 2, tg = lane & 3;
    #pragma unroll
    for (int mt = 0; mt < 4; mt++)
        #pragma unroll
        for (int nt = 0; nt < 4; nt++) {
            const int row = row0 + wm + mt * 16 + g;
            const int col = col0 + wn + nt * 8 + tg * 2;
            if (SPLIT_OUT) {
                __nv_bfloat16 h0, l0, h1, l1;
                bsplit(c[mt][nt][0], h0, l0);
                bsplit(c[mt][nt][1], h1, l1);
                __nv_bfloat162 hh; hh.x = h0; hh.y = h1;
                __nv_bfloat162 ll; ll.x = l0; ll.y = l1;
                *(__nv_bfloat162*)(Chi + (size_t)row * N + col) = hh;
                *(__nv_bfloat162*)(Clo + (size_t)row * N + col) = ll;
                bsplit(c[mt][nt][2], h0, l0);
                bsplit(c[mt][nt][3], h1, l1);
                hh.x = h0; hh.y = h1; ll.x = l0; ll.y = l1;
                *(__nv_bfloat162*)(Chi + (size_t)(row + 8) * N + col) = hh;
                *(__nv_bfloat162*)(Clo + (size_t)(row + 8) * N + col) = ll;
            } else {
                *(float2*)(Cf + (size_t)row * N + col) = make_float2(c[mt][nt][0], c[mt][nt][1]);
                *(float2*)(Cf + (size_t)(row + 8) * N + col) = make_float2(c[mt][nt][2], c[mt][nt][3]);
            }
        }
}

// ---------------------------------------------------------------------------
// Scores: S = (Q.K^T)/8 for lower-triangular 128x128 tile pairs. K-dim = 64.
// ---------------------------------------------------------------------------
#define SMEM_S (4 * 128 * LDT * 2)

__global__ __launch_bounds__(256, 2) void scores_mma(const __nv_bfloat16* __restrict__ qh,
                                                     const __nv_bfloat16* __restrict__ ql,
                                                     float* __restrict__ attn)
{
    const int t = blockIdx.x, h = blockIdx.y, b = blockIdx.z;
    int i = 0;
    while ((i + 1) * (i + 2) / 2 <= t) i++;
    const int j = t - i * (i + 1) / 2;

    extern __shared__ __nv_bfloat16 sm[];
    const uint32_t smb = smem_u32(sm);
    const uint32_t sQh = smb;
    const uint32_t sQl = smb + 128*LDT*2;
    const uint32_t sKh = smb + 2*128*LDT*2;
    const uint32_t sKl = smb + 3*128*LDT*2;

    const int tid = threadIdx.x, lane = tid & 31, wid = tid >> 5;
    const int wm = (wid >> 2) * 64, wn = (wid & 3) * 32;
    const int lrow = lane & 15, lcol = (lane >> 4) * 8;

    {
        const int r_ = tid >> 3, cb_ = (tid & 7) * 8;
        #pragma unroll
        for (int rr = 0; rr < 4; rr++) {
            int r = r_ + rr * 32;
            uint32_t so = (uint32_t)(r * LDT + cb_) * 2;
            size_t qa = (size_t)(b * N_SEQ + i * 128 + r) * QKV_COLS + h * 64 + cb_;
            size_t ka = (size_t)(b * N_SEQ + j * 128 + r) * QKV_COLS + D_MODEL + h * 64 + cb_;
            cpa16(sQh + so, qh + qa);
            cpa16(sQl + so, ql + qa);
            cpa16(sKh + so, qh + ka);
            cpa16(sKl + so, ql + ka);
        }
        CP_COMMIT();
        CP_WAIT0();
    }
    __syncthreads();

    float c[4][4][4] = {};
    #pragma unroll
    for (int kt = 0; kt < 4; kt++) {
        uint32_t ah[4][4], al[4][4], bh[2][4], bl[2][4];
        #pragma unroll
        for (int mt = 0; mt < 4; mt++) {
            uint32_t off = ((wm + mt * 16 + lrow) * LDT + kt * 16 + lcol) * 2;
            ldsm4(ah[mt], sQh + off);
            ldsm4(al[mt], sQl + off);
        }
        #pragma unroll
        for (int bt = 0; bt < 2; bt++) {
            uint32_t off = ((wn + bt * 16 + lrow) * LDT + kt * 16 + lcol) * 2;
            ldsm4(bh[bt], sKh + off);
            ldsm4(bl[bt], sKl + off);
        }
        #pragma unroll
        for (int mt = 0; mt < 4; mt++)
            #pragma unroll
            for (int nt = 0; nt < 4; nt++) {
                const int bt = nt >> 1, s = nt & 1;
                mma16816(c[mt][nt], ah[mt], bh[bt][s], bh[bt][s + 2]);
                mma16816(c[mt][nt], al[mt], bh[bt][s], bh[bt][s + 2]);
                mma16816(c[mt][nt], ah[mt], bl[bt][s], bl[bt][s + 2]);
            }
    }

    float* base = attn + ((size_t)(b * N_HEADS + h)) * N_SEQ * N_SEQ;
    const int g = lane >> 2, tg = lane & 3;
    #pragma unroll
    for (int mt = 0; mt < 4; mt++)
        #pragma unroll
        for (int nt = 0; nt < 4; nt++) {
            const int q = i * 128 + wm + mt * 16 + g;
            const int col = j * 128 + wn + nt * 8 + tg * 2;
            *(float2*)(base + (size_t)q * N_SEQ + col) =
                make_float2(c[mt][nt][0] * 0.125f, c[mt][nt][1] * 0.125f);
            *(float2*)(base + (size_t)(q + 8) * N_SEQ + col) =
                make_float2(c[mt][nt][2] * 0.125f, c[mt][nt][3] * 0.125f);
        }
}

// ---------------------------------------------------------------------------
// One-pass softmax: row (<=2048 floats = 8 regs/thread) read ONCE into
// registers; max+sum reduced; P written (with zero upper-triangle) from regs.
// ---------------------------------------------------------------------------
__global__ __launch_bounds__(256) void softmax1p(float* __restrict__ attn)
{
    const int n = blockIdx.x, h = blockIdx.y, b = blockIdx.z;
    const int tid = threadIdx.x;
    float* row = attn + ((size_t)(b * N_HEADS + h) * N_SEQ + n) * N_SEQ;

    __shared__ float red[256];
    const int P = n + 1, n4 = P >> 2, tail = P & 3;

    // read prefix once: each thread owns float4 groups tid, tid+256
    float4 v[2];
    int cnt = 0;
    float lmax = -INFINITY;
    #pragma unroll
    for (int k = 0; k < 2; k++) {
        int m4 = tid + k * 256;
        if (m4 < n4) {
            float4 x = *(const float4*)&row[m4 * 4];
            v[cnt++] = x;
            lmax = fmaxf(lmax, fmaxf(fmaxf(x.x, x.y), fmaxf(x.z, x.w)));
        }
    }
    float tv = 0.f;
    const bool hasT = (tid < tail);
    if (hasT) { tv = row[n4 * 4 + tid]; lmax = fmaxf(lmax, tv); }

    red[tid] = lmax;
    __syncthreads();
    #pragma unroll
    for (int s = 128; s > 0; s >>= 1) {
        if (tid < s) red[tid] = fmaxf(red[tid], red[tid + s]);
        __syncthreads();
    }
    const float mx = red[0];
    __syncthreads();

    float ls = 0.f;
    for (int k = 0; k < cnt; k++)
        ls += __expf(v[k].x - mx) + __expf(v[k].y - mx) +
              __expf(v[k].z - mx) + __expf(v[k].w - mx);
    if (hasT) ls += __expf(tv - mx);
    red[tid] = ls;
    __syncthreads();
    #pragma unroll
    for (int s = 128; s > 0; s >>= 1) {
        if (tid < s) red[tid] += red[tid + s];
        __syncthreads();
    }
    const float inv = 1.f / red[0];

    // write whole row from registers (prefix) + zeros (rest); tail group
    // re-read once (at most one 16B load per row).
    cnt = 0;
    #pragma unroll
    for (int k = 0; k < 2; k++) {
        int m4 = tid + k * 256;
        float4 o;
        if (m4 < n4) {
            float4 x = v[cnt++];
            o.x = __expf(x.x - mx) * inv;
            o.y = __expf(x.y - mx) * inv;
            o.z = __expf(x.z - mx) * inv;
            o.w = __expf(x.w - mx) * inv;
        } else if (m4 == n4 && tail) {
            float4 x = *(const float4*)&row[m4 * 4];
            float xx[4] = {x.x, x.y, x.z, x.w};
            float oo[4];
            #pragma unroll
            for (int q = 0; q < 4; q++)
                oo[q] = (m4 * 4 + q < P) ? __expf(xx[q] - mx) * inv : 0.f;
            o = make_float4(oo[0], oo[1], oo[2], oo[3]);
        } else {
            o = make_float4(0.f, 0.f, 0.f, 0.f);
        }
        *(float4*)&row[m4 * 4] = o;
    }
}

// ---------------------------------------------------------------------------
// PV (Round-5 proven form, heavy tiles first): ctx = P @ V, split P in smem.
// ---------------------------------------------------------------------------
#define LDP 136
#define SMEM_PV ((2 * 128 * LDP + 2 * 128 * LDT) * 2)   // 106496 B

__global__ __launch_bounds__(256) void pv_mma(const float* __restrict__ attn,
                                              const __nv_bfloat16* __restrict__ qh,
                                              const __nv_bfloat16* __restrict__ ql,
                                              __nv_bfloat16* __restrict__ ch,
                                              __nv_bfloat16* __restrict__ cl)
{
    const int i = NT128 - 1 - blockIdx.x;   // heavy first
    const int h = blockIdx.y, b = blockIdx.z;

    extern __shared__ __nv_bfloat16 sm[];
    __nv_bfloat16* Ph = sm;
    __nv_bfloat16* Pl = Ph + 128 * LDP;
    __nv_bfloat16* Vh = Pl + 128 * LDP;
    __nv_bfloat16* Vl = Vh + 128 * LDT;

    const int tid = threadIdx.x, lane = tid & 31, wid = tid >> 5;
    const int wm = (wid >> 1) * 32, wn = (wid & 1) * 32;
    const int lrow = lane & 15, lcol = (lane >> 4) * 8;

    const uint32_t sPh = smem_u32(Ph), sPl = smem_u32(Pl);
    const uint32_t sVh = smem_u32(Vh), sVl = smem_u32(Vl);

    const float* base = attn + ((size_t)(b * N_HEADS + h)) * N_SEQ * N_SEQ
                             + (size_t)i * 128 * N_SEQ;
    float c[2][4][4] = {};

    for (int j = 0; j <= i; j++) {
        if (j) __syncthreads();
        // V tile via cp.async (overlaps the P convert below)
        {
            const int r_ = tid >> 3, cb_ = (tid & 7) * 8;
            #pragma unroll
            for (int rr = 0; rr < 4; rr++) {
                int r = r_ + rr * 32;
                uint32_t so = (uint32_t)(r * LDT + cb_) * 2;
                size_t va = (size_t)(b * N_SEQ + j * 128 + r) * QKV_COLS + 2 * D_MODEL + h * 64 + cb_;
                cpa16(sVh + so, qh + va);
                cpa16(sVl + so, ql + va);
            }
            CP_COMMIT();
        }
        // P tile 128x128 fp32 -> split hi/lo bf16 in smem
        for (int e = tid; e < 4096; e += 256) {
            int r = e >> 5, c4 = (e & 31) * 4;
            float4 v = *(const float4*)(base + (size_t)r * N_SEQ + j * 128 + c4);
            float vv[4] = {v.x, v.y, v.z, v.w};
            __nv_bfloat16 hh[4], ll[4];
            #pragma unroll
            for (int k = 0; k < 4; k++) bsplit(vv[k], hh[k], ll[k]);
            *(uint2*)(Ph + r * LDP + c4) = *(uint2*)hh;
            *(uint2*)(Pl + r * LDP + c4) = *(uint2*)ll;
        }
        CP_WAIT0();
        __syncthreads();

        #pragma unroll
        for (int kt = 0; kt < 8; kt++) {
            uint32_t ah[2][4], al[2][4], vh[2][4], vl[2][4];
            #pragma unroll
            for (int mt = 0; mt < 2; mt++) {
                uint32_t off = ((wm + mt * 16 + lrow) * LDP + kt * 16 + lcol) * 2;
                ldsm4(ah[mt], sPh + off);
                ldsm4(al[mt], sPl + off);
            }
            #pragma unroll
            for (int bt = 0; bt < 2; bt++) {
                uint32_t off = ((kt * 16 + lrow) * LDT + wn + bt * 16 + lcol) * 2;
                ldsm4t(vh[bt], sVh + off);
                ldsm4t(vl[bt], sVl + off);
            }
            #pragma unroll
            for (int mt = 0; mt < 2; mt++)
                #pragma unroll
                for (int nt = 0; nt < 4; nt++) {
                    const int bt = nt >> 1, s = (nt & 1) * 2;
                    mma16816(c[mt][nt], ah[mt], vh[bt][s], vh[bt][s + 1]);
                    mma16816(c[mt][nt], al[mt], vh[bt][s], vh[bt][s + 1]);
                    mma16816(c[mt][nt], ah[mt], vl[bt][s], vl[bt][s + 1]);
                }
        }
    }

    const int g = lane >> 2, tg = lane & 3;
    #pragma unroll
    for (int mt = 0; mt < 2; mt++)
        #pragma unroll
        for (int nt = 0; nt < 4; nt++) {
            const int q = i * 128 + wm + mt * 16 + g;
            const int d = wn + nt * 8 + tg * 2;
            __nv_bfloat16 h0, l0, h1, l1;
            bsplit(c[mt][nt][0], h0, l0);
            bsplit(c[mt][nt][1], h1, l1);
            __nv_bfloat162 hh; hh.x = h0; hh.y = h1;
            __nv_bfloat162 ll; ll.x = l0; ll.y = l1;
            *(__nv_bfloat162*)(ch + (size_t)(b * N_SEQ + q) * D_MODEL + h * 64 + d) = hh;
            *(__nv_bfloat162*)(cl + (size_t)(b * N_SEQ + q) * D_MODEL + h * 64 + d) = ll;
            bsplit(c[mt][nt][2], h0, l0);
            bsplit(c[mt][nt][3], h1, l1);
            hh.x = h0; hh.y = h1; ll.x = l0; ll.y = l1;
            *(__nv_bfloat162*)(ch + (size_t)(b * N_SEQ + q + 8) * D_MODEL + h * 64 + d) = hh;
            *(__nv_bfloat162*)(cl + (size_t)(b * N_SEQ + q + 8) * D_MODEL + h * 64 + d) = ll;
        }
}

// ---------------------------------------------------------------------------
extern "C" void kernel_launch(void* const* d_in, const int* in_sizes, int n_in,
                              void* d_out, int out_size)
{
    const float* x     = (const float*)d_in[0];
    const float* W_qkv = (const float*)d_in[1];
    const float* W_out = (const float*)d_in[2];
    float* out = (float*)d_out;

    float* attn_scratch;
    __nv_bfloat16 *xh, *xl, *qkvh, *qkvl, *ch, *cl, *wqh, *wql, *woh, *wol;
    cudaGetSymbolAddress((void**)&attn_scratch, g_attn);
    cudaGetSymbolAddress((void**)&xh, g_xh);
    cudaGetSymbolAddress((void**)&xl, g_xl);
    cudaGetSymbolAddress((void**)&qkvh, g_qkvh);
    cudaGetSymbolAddress((void**)&qkvl, g_qkvl);
    cudaGetSymbolAddress((void**)&ch, g_ch);
    cudaGetSymbolAddress((void**)&cl, g_cl);
    cudaGetSymbolAddress((void**)&wqh, g_wqh);
    cudaGetSymbolAddress((void**)&wql, g_wql);
    cudaGetSymbolAddress((void**)&woh, g_woh);
    cudaGetSymbolAddress((void**)&wol, g_wol);

    cudaFuncSetAttribute(gemm_mma<true>,  cudaFuncAttributeMaxDynamicSharedMemorySize, SMEM_G);
    cudaFuncSetAttribute(gemm_mma<false>, cudaFuncAttributeMaxDynamicSharedMemorySize, SMEM_G);
    cudaFuncSetAttribute(scores_mma,      cudaFuncAttributeMaxDynamicSharedMemorySize, SMEM_S);
    cudaFuncSetAttribute(pv_mma,          cudaFuncAttributeMaxDynamicSharedMemorySize, SMEM_PV);

    const long long out_elems  = (long long)B_SZ * N_SEQ * D_MODEL;
    const long long attn_elems = (long long)B_SZ * N_HEADS * N_SEQ * N_SEQ;
    const int write_attn = ((long long)out_size >= out_elems + attn_elems) ? 1 : 0;
    float* attn_buf = write_attn ? (out + out_elems) : attn_scratch;

    // 0) prep
    split_kernel<<<(M_ROWS * D_MODEL) / 1024, 256>>>(x, xh, xl);
    {
        dim3 grid(QKV_COLS / 32, D_MODEL / 32);
        wtrans_split<<<grid, dim3(32, 8)>>>(W_qkv, wqh, wql, D_MODEL, QKV_COLS);
    }
    {
        dim3 grid(D_MODEL / 32, D_MODEL / 32);
        wtrans_split<<<grid, dim3(32, 8)>>>(W_out, woh, wol, D_MODEL, D_MODEL);
    }

    // 1) QKV projection -> split bf16 qkv
    {
        dim3 grid(QKV_COLS / 128, M_ROWS / 128);
        gemm_mma<true><<<grid, 256, SMEM_G>>>(xh, xl, wqh, wql,
                                              nullptr, qkvh, qkvl, QKV_COLS, D_MODEL);
    }
    // 2a) raw scores
    {
        dim3 grid(NPAIR128, N_HEADS, B_SZ);
        scores_mma<<<grid, 256, SMEM_S>>>(qkvh, qkvl, attn_buf);
    }
    // 2b) one-pass softmax (read prefix once; write P + zeros once)
    {
        dim3 grid(N_SEQ, N_HEADS, B_SZ);
        softmax1p<<<grid, 256>>>(attn_buf);
    }
    // 2c) P @ V -> split bf16 ctx
    {
        dim3 grid(NT128, N_HEADS, B_SZ);
        pv_mma<<<grid, 256, SMEM_PV>>>(attn_buf, qkvh, qkvl, ch, cl);
    }
    // 3) output projection -> fp32 out
    {
        dim3 grid(D_MODEL / 128, M_ROWS / 128);
        gemm_mma<false><<<grid, 256, SMEM_G>>>(ch, cl, woh, wol,
                                               out, nullptr, nullptr, D_MODEL, D_MODEL);
    }
}

// round 13
// speedup vs baseline: 1.6499x; 1.0583x over previous
#include <cuda_runtime.h>
#include <cuda_bf16.h>
#include <math.h>
#include <stdint.h>

#define B_SZ    2
#define N_SEQ   2048
#define D_MODEL 1024
#define N_HEADS 16
#define D_HEAD  64
#define M_ROWS  (B_SZ * N_SEQ)        // 4096
#define QKV_COLS (3 * D_MODEL)        // 3072
#define NT128   (N_SEQ / 128)         // 16
#define NPAIR128 (NT128 * (NT128 + 1) / 2)  // 136

// ---------------- scratch ---------------------------------------------------
__device__ float g_attn[(size_t)B_SZ * N_HEADS * N_SEQ * N_SEQ];      // fallback
__device__ __nv_bfloat16 g_ph[(size_t)B_SZ * N_HEADS * N_SEQ * N_SEQ];
__device__ __nv_bfloat16 g_pl[(size_t)B_SZ * N_HEADS * N_SEQ * N_SEQ];
__device__ __nv_bfloat16 g_xh[(size_t)M_ROWS * D_MODEL];
__device__ __nv_bfloat16 g_xl[(size_t)M_ROWS * D_MODEL];
__device__ __nv_bfloat16 g_qkvh[(size_t)M_ROWS * QKV_COLS];
__device__ __nv_bfloat16 g_qkvl[(size_t)M_ROWS * QKV_COLS];
__device__ __nv_bfloat16 g_ch[(size_t)M_ROWS * D_MODEL];
__device__ __nv_bfloat16 g_cl[(size_t)M_ROWS * D_MODEL];
__device__ __nv_bfloat16 g_wqh[(size_t)QKV_COLS * D_MODEL];   // [N][K]
__device__ __nv_bfloat16 g_wql[(size_t)QKV_COLS * D_MODEL];
__device__ __nv_bfloat16 g_woh[(size_t)D_MODEL * D_MODEL];
__device__ __nv_bfloat16 g_wol[(size_t)D_MODEL * D_MODEL];

// ---------------- helpers ----------------------------------------------------
__device__ __forceinline__ uint32_t smem_u32(const void* p) {
    uint32_t a;
    asm("{ .reg .u64 t; cvta.to.shared.u64 t, %1; cvt.u32.u64 %0, t; }" : "=r"(a) : "l"(p));
    return a;
}
__device__ __forceinline__ void ldsm4(uint32_t* r, uint32_t a) {
    asm volatile("ldmatrix.sync.aligned.m8n8.x4.shared.b16 {%0,%1,%2,%3}, [%4];"
                 : "=r"(r[0]), "=r"(r[1]), "=r"(r[2]), "=r"(r[3]) : "r"(a));
}
__device__ __forceinline__ void ldsm4t(uint32_t* r, uint32_t a) {
    asm volatile("ldmatrix.sync.aligned.m8n8.x4.trans.shared.b16 {%0,%1,%2,%3}, [%4];"
                 : "=r"(r[0]), "=r"(r[1]), "=r"(r[2]), "=r"(r[3]) : "r"(a));
}
__device__ __forceinline__ void mma16816(float* c, const uint32_t* a, uint32_t b0, uint32_t b1) {
    asm volatile("mma.sync.aligned.m16n8k16.row.col.f32.bf16.bf16.f32 "
                 "{%0,%1,%2,%3}, {%4,%5,%6,%7}, {%8,%9}, {%0,%1,%2,%3};"
                 : "+f"(c[0]), "+f"(c[1]), "+f"(c[2]), "+f"(c[3])
                 : "r"(a[0]), "r"(a[1]), "r"(a[2]), "r"(a[3]), "r"(b0), "r"(b1));
}
__device__ __forceinline__ void bsplit(float v, __nv_bfloat16& h, __nv_bfloat16& l) {
    h = __float2bfloat16(v);
    l = __float2bfloat16(v - __bfloat162float(h));
}
__device__ __forceinline__ void cpa16(uint32_t saddr, const void* g) {
    asm volatile("cp.async.cg.shared.global [%0], [%1], 16;" :: "r"(saddr), "l"(g));
}
#define CP_COMMIT() asm volatile("cp.async.commit_group;" ::: "memory")
#define CP_WAIT0()  asm volatile("cp.async.wait_group 0;" ::: "memory")

// ---------------------------------------------------------------------------
// prep kernels
// ---------------------------------------------------------------------------
__global__ __launch_bounds__(256) void split_kernel(const float* __restrict__ s,
                                                    __nv_bfloat16* __restrict__ hi,
                                                    __nv_bfloat16* __restrict__ lo)
{
    size_t i = (size_t)blockIdx.x * 1024 + threadIdx.x * 4;
    float4 v = *(const float4*)&s[i];
    float vv[4] = {v.x, v.y, v.z, v.w};
    __nv_bfloat16 h[4], l[4];
    #pragma unroll
    for (int k = 0; k < 4; k++) bsplit(vv[k], h[k], l[k]);
    *(uint2*)&hi[i] = *(uint2*)h;
    *(uint2*)&lo[i] = *(uint2*)l;
}

// W[K][N] -> hi/lo[N][K]
__global__ void wtrans_split(const float* __restrict__ W,
                             __nv_bfloat16* __restrict__ hi,
                             __nv_bfloat16* __restrict__ lo, int K, int N)
{
    __shared__ float t[32][33];
    const int n0 = blockIdx.x * 32, k0 = blockIdx.y * 32;
    const int tx = threadIdx.x, ty = threadIdx.y;  // (32,8)
    for (int i = ty; i < 32; i += 8)
        t[i][tx] = W[(size_t)(k0 + i) * N + n0 + tx];
    __syncthreads();
    for (int i = ty; i < 32; i += 8) {
        float v = t[tx][i];
        __nv_bfloat16 h, l;
        bsplit(v, h, l);
        hi[(size_t)(n0 + i) * K + k0 + tx] = h;
        lo[(size_t)(n0 + i) * K + k0 + tx] = l;
    }
}

// ---------------------------------------------------------------------------
// GEMM (Round-5 proven form): mma.sync, single-stage smem, BK=64.
// ---------------------------------------------------------------------------
#define LDT 72
#define SMEM_G (4 * 128 * LDT * 2)   // 73728 B

template<bool SPLIT_OUT>
__global__ __launch_bounds__(256) void gemm_mma(const __nv_bfloat16* __restrict__ ahi,
                                                const __nv_bfloat16* __restrict__ alo,
                                                const __nv_bfloat16* __restrict__ bhi,
                                                const __nv_bfloat16* __restrict__ blo,
                                                float* __restrict__ Cf,
                                                __nv_bfloat16* __restrict__ Chi,
                                                __nv_bfloat16* __restrict__ Clo,
                                                int N, int K)
{
    extern __shared__ __nv_bfloat16 sm[];
    __nv_bfloat16* Ah = sm;
    __nv_bfloat16* Al = Ah + 128 * LDT;
    __nv_bfloat16* Bh = Al + 128 * LDT;
    __nv_bfloat16* Bl = Bh + 128 * LDT;

    const int tid = threadIdx.x, lane = tid & 31, wid = tid >> 5;
    const int wm = (wid >> 2) * 64, wn = (wid & 3) * 32;
    const int row0 = blockIdx.y * 128, col0 = blockIdx.x * 128;
    const int lrow = lane & 15;
    const int lcol = (lane >> 4) * 8;

    const uint32_t sAh = smem_u32(Ah), sAl = smem_u32(Al);
    const uint32_t sBh = smem_u32(Bh), sBl = smem_u32(Bl);

    float c[4][4][4] = {};

    for (int k0 = 0; k0 < K; k0 += 64) {
        for (int e = tid; e < 1024; e += 256) {
            int r = e >> 3, cb = (e & 7) * 8;
            size_t ga = (size_t)(row0 + r) * K + k0 + cb;
            size_t gb = (size_t)(col0 + r) * K + k0 + cb;
            *(uint4*)(Ah + r * LDT + cb) = *(const uint4*)(ahi + ga);
            *(uint4*)(Al + r * LDT + cb) = *(const uint4*)(alo + ga);
            *(uint4*)(Bh + r * LDT + cb) = *(const uint4*)(bhi + gb);
            *(uint4*)(Bl + r * LDT + cb) = *(const uint4*)(blo + gb);
        }
        __syncthreads();

        #pragma unroll
        for (int kt = 0; kt < 4; kt++) {
            uint32_t ah[4][4], al[4][4], bh[2][4], bl[2][4];
            #pragma unroll
            for (int mt = 0; mt < 4; mt++) {
                uint32_t off = ((wm + mt * 16 + lrow) * LDT + kt * 16 + lcol) * 2;
                ldsm4(ah[mt], sAh + off);
                ldsm4(al[mt], sAl + off);
            }
            #pragma unroll
            for (int bt = 0; bt < 2; bt++) {
                uint32_t off = ((wn + bt * 16 + lrow) * LDT + kt * 16 + lcol) * 2;
                ldsm4(bh[bt], sBh + off);
                ldsm4(bl[bt], sBl + off);
            }
            #pragma unroll
            for (int mt = 0; mt < 4; mt++)
                #pragma unroll
                for (int nt = 0; nt < 4; nt++) {
                    const int bt = nt >> 1, s = nt & 1;
                    mma16816(c[mt][nt], ah[mt], bh[bt][s], bh[bt][s + 2]);
                    mma16816(c[mt][nt], al[mt], bh[bt][s], bh[bt][s + 2]);
                    mma16816(c[mt][nt], ah[mt], bl[bt][s], bl[bt][s + 2]);
                }
        }
        __syncthreads();
    }

    const int g = lane >> 2, tg = lane & 3;
    #pragma unroll
    for (int mt = 0; mt < 4; mt++)
        #pragma unroll
        for (int nt = 0; nt < 4; nt++) {
            const int row = row0 + wm + mt * 16 + g;
            const int col = col0 + wn + nt * 8 + tg * 2;
            if (SPLIT_OUT) {
                __nv_bfloat16 h0, l0, h1, l1;
                bsplit(c[mt][nt][0], h0, l0);
                bsplit(c[mt][nt][1], h1, l1);
                __nv_bfloat162 hh; hh.x = h0; hh.y = h1;
                __nv_bfloat162 ll; ll.x = l0; ll.y = l1;
                *(__nv_bfloat162*)(Chi + (size_t)row * N + col) = hh;
                *(__nv_bfloat162*)(Clo + (size_t)row * N + col) = ll;
                bsplit(c[mt][nt][2], h0, l0);
                bsplit(c[mt][nt][3], h1, l1);
                hh.x = h0; hh.y = h1; ll.x = l0; ll.y = l1;
                *(__nv_bfloat162*)(Chi + (size_t)(row + 8) * N + col) = hh;
                *(__nv_bfloat162*)(Clo + (size_t)(row + 8) * N + col) = ll;
            } else {
                *(float2*)(Cf + (size_t)row * N + col) = make_float2(c[mt][nt][0], c[mt][nt][1]);
                *(float2*)(Cf + (size_t)(row + 8) * N + col) = make_float2(c[mt][nt][2], c[mt][nt][3]);
            }
        }
}

// ---------------------------------------------------------------------------
// Scores: S = (Q.K^T)/8 for lower-triangular 128x128 tile pairs. K-dim = 64.
// ---------------------------------------------------------------------------
#define SMEM_S (4 * 128 * LDT * 2)

__global__ __launch_bounds__(256, 2) void scores_mma(const __nv_bfloat16* __restrict__ qh,
                                                     const __nv_bfloat16* __restrict__ ql,
                                                     float* __restrict__ attn)
{
    const int t = blockIdx.x, h = blockIdx.y, b = blockIdx.z;
    int i = 0;
    while ((i + 1) * (i + 2) / 2 <= t) i++;
    const int j = t - i * (i + 1) / 2;

    extern __shared__ __nv_bfloat16 sm[];
    const uint32_t smb = smem_u32(sm);
    const uint32_t sQh = smb;
    const uint32_t sQl = smb + 128*LDT*2;
    const uint32_t sKh = smb + 2*128*LDT*2;
    const uint32_t sKl = smb + 3*128*LDT*2;

    const int tid = threadIdx.x, lane = tid & 31, wid = tid >> 5;
    const int wm = (wid >> 2) * 64, wn = (wid & 3) * 32;
    const int lrow = lane & 15, lcol = (lane >> 4) * 8;

    {
        const int r_ = tid >> 3, cb_ = (tid & 7) * 8;
        #pragma unroll
        for (int rr = 0; rr < 4; rr++) {
            int r = r_ + rr * 32;
            uint32_t so = (uint32_t)(r * LDT + cb_) * 2;
            size_t qa = (size_t)(b * N_SEQ + i * 128 + r) * QKV_COLS + h * 64 + cb_;
            size_t ka = (size_t)(b * N_SEQ + j * 128 + r) * QKV_COLS + D_MODEL + h * 64 + cb_;
            cpa16(sQh + so, qh + qa);
            cpa16(sQl + so, ql + qa);
            cpa16(sKh + so, qh + ka);
            cpa16(sKl + so, ql + ka);
        }
        CP_COMMIT();
        CP_WAIT0();
    }
    __syncthreads();

    float c[4][4][4] = {};
    #pragma unroll
    for (int kt = 0; kt < 4; kt++) {
        uint32_t ah[4][4], al[4][4], bh[2][4], bl[2][4];
        #pragma unroll
        for (int mt = 0; mt < 4; mt++) {
            uint32_t off = ((wm + mt * 16 + lrow) * LDT + kt * 16 + lcol) * 2;
            ldsm4(ah[mt], sQh + off);
            ldsm4(al[mt], sQl + off);
        }
        #pragma unroll
        for (int bt = 0; bt < 2; bt++) {
            uint32_t off = ((wn + bt * 16 + lrow) * LDT + kt * 16 + lcol) * 2;
            ldsm4(bh[bt], sKh + off);
            ldsm4(bl[bt], sKl + off);
        }
        #pragma unroll
        for (int mt = 0; mt < 4; mt++)
            #pragma unroll
            for (int nt = 0; nt < 4; nt++) {
                const int bt = nt >> 1, s = nt & 1;
                mma16816(c[mt][nt], ah[mt], bh[bt][s], bh[bt][s + 2]);
                mma16816(c[mt][nt], al[mt], bh[bt][s], bh[bt][s + 2]);
                mma16816(c[mt][nt], ah[mt], bl[bt][s], bl[bt][s + 2]);
            }
    }

    float* base = attn + ((size_t)(b * N_HEADS + h)) * N_SEQ * N_SEQ;
    const int g = lane >> 2, tg = lane & 3;
    #pragma unroll
    for (int mt = 0; mt < 4; mt++)
        #pragma unroll
        for (int nt = 0; nt < 4; nt++) {
            const int q = i * 128 + wm + mt * 16 + g;
            const int col = j * 128 + wn + nt * 8 + tg * 2;
            *(float2*)(base + (size_t)q * N_SEQ + col) =
                make_float2(c[mt][nt][0] * 0.125f, c[mt][nt][1] * 0.125f);
            *(float2*)(base + (size_t)(q + 8) * N_SEQ + col) =
                make_float2(c[mt][nt][2] * 0.125f, c[mt][nt][3] * 0.125f);
        }
}

// ---------------------------------------------------------------------------
// One-pass softmax; also emits split-bf16 P (Ph/Pl) for the causal tile span
// so pv can cp.async them directly (split is bit-identical to pv's old one).
// ---------------------------------------------------------------------------
__global__ __launch_bounds__(256) void softmax1p(float* __restrict__ attn,
                                                 __nv_bfloat16* __restrict__ ph,
                                                 __nv_bfloat16* __restrict__ pl)
{
    const int n = blockIdx.x, h = blockIdx.y, b = blockIdx.z;
    const int tid = threadIdx.x;
    const size_t rowbase = ((size_t)(b * N_HEADS + h) * N_SEQ + n) * N_SEQ;
    float* row = attn + rowbase;

    __shared__ float red[256];
    const int P = n + 1, n4 = P >> 2, tail = P & 3;
    const int cover4 = (((P + 127) >> 7) << 5);   // float4 groups covering causal tiles

    float4 v[2];
    int cnt = 0;
    float lmax = -INFINITY;
    #pragma unroll
    for (int k = 0; k < 2; k++) {
        int m4 = tid + k * 256;
        if (m4 < n4) {
            float4 x = *(const float4*)&row[m4 * 4];
            v[cnt++] = x;
            lmax = fmaxf(lmax, fmaxf(fmaxf(x.x, x.y), fmaxf(x.z, x.w)));
        }
    }
    float tv = 0.f;
    const bool hasT = (tid < tail);
    if (hasT) { tv = row[n4 * 4 + tid]; lmax = fmaxf(lmax, tv); }

    red[tid] = lmax;
    __syncthreads();
    #pragma unroll
    for (int s = 128; s > 0; s >>= 1) {
        if (tid < s) red[tid] = fmaxf(red[tid], red[tid + s]);
        __syncthreads();
    }
    const float mx = red[0];
    __syncthreads();

    float ls = 0.f;
    for (int k = 0; k < cnt; k++)
        ls += __expf(v[k].x - mx) + __expf(v[k].y - mx) +
              __expf(v[k].z - mx) + __expf(v[k].w - mx);
    if (hasT) ls += __expf(tv - mx);
    red[tid] = ls;
    __syncthreads();
    #pragma unroll
    for (int s = 128; s > 0; s >>= 1) {
        if (tid < s) red[tid] += red[tid + s];
        __syncthreads();
    }
    const float inv = 1.f / red[0];

    cnt = 0;
    #pragma unroll
    for (int k = 0; k < 2; k++) {
        int m4 = tid + k * 256;
        float4 o;
        if (m4 < n4) {
            float4 x = v[cnt++];
            o.x = __expf(x.x - mx) * inv;
            o.y = __expf(x.y - mx) * inv;
            o.z = __expf(x.z - mx) * inv;
            o.w = __expf(x.w - mx) * inv;
        } else if (m4 == n4 && tail) {
            float4 x = *(const float4*)&row[m4 * 4];
            float xx[4] = {x.x, x.y, x.z, x.w};
            float oo[4];
            #pragma unroll
            for (int q = 0; q < 4; q++)
                oo[q] = (m4 * 4 + q < P) ? __expf(xx[q] - mx) * inv : 0.f;
            o = make_float4(oo[0], oo[1], oo[2], oo[3]);
        } else {
            o = make_float4(0.f, 0.f, 0.f, 0.f);
        }
        *(float4*)&row[m4 * 4] = o;

        if (m4 < cover4) {
            float oo[4] = {o.x, o.y, o.z, o.w};
            __nv_bfloat16 hh[4], ll[4];
            #pragma unroll
            for (int q = 0; q < 4; q++) bsplit(oo[q], hh[q], ll[q]);
            *(uint2*)&ph[rowbase + m4 * 4] = *(uint2*)hh;
            *(uint2*)&pl[rowbase + m4 * 4] = *(uint2*)ll;
        }
    }
}

// ---------------------------------------------------------------------------
// PV: ctx = P @ V; all operand tiles (Ph,Pl,Vh,Vl) pulled via cp.async.
// ---------------------------------------------------------------------------
#define LDP 136
#define SMEM_PV ((2 * 128 * LDP + 2 * 128 * LDT) * 2)   // 106496 B

__global__ __launch_bounds__(256) void pv_mma(const __nv_bfloat16* __restrict__ ph,
                                              const __nv_bfloat16* __restrict__ pl,
                                              const __nv_bfloat16* __restrict__ qh,
                                              const __nv_bfloat16* __restrict__ ql,
                                              __nv_bfloat16* __restrict__ ch,
                                              __nv_bfloat16* __restrict__ cl)
{
    const int i = NT128 - 1 - blockIdx.x;   // heavy first
    const int h = blockIdx.y, b = blockIdx.z;

    extern __shared__ __nv_bfloat16 sm[];
    __nv_bfloat16* Ph = sm;
    __nv_bfloat16* Pl = Ph + 128 * LDP;
    __nv_bfloat16* Vh = Pl + 128 * LDP;
    __nv_bfloat16* Vl = Vh + 128 * LDT;

    const int tid = threadIdx.x, lane = tid & 31, wid = tid >> 5;
    const int wm = (wid >> 1) * 32, wn = (wid & 1) * 32;
    const int lrow = lane & 15, lcol = (lane >> 4) * 8;

    const uint32_t sPh = smem_u32(Ph), sPl = smem_u32(Pl);
    const uint32_t sVh = smem_u32(Vh), sVl = smem_u32(Vl);

    const size_t pbase = ((size_t)(b * N_HEADS + h)) * N_SEQ * N_SEQ
                       + (size_t)i * 128 * N_SEQ;
    float c[2][4][4] = {};

    for (int j = 0; j <= i; j++) {
        if (j) __syncthreads();
        // P tiles (hi/lo): 128 rows x 16 16B-chunks each
        for (int e = tid; e < 2048; e += 256) {
            int r = e >> 4, cc = e & 15;
            uint32_t so = (uint32_t)(r * LDP + cc * 8) * 2;
            size_t ga = pbase + (size_t)r * N_SEQ + j * 128 + cc * 8;
            cpa16(sPh + so, ph + ga);
            cpa16(sPl + so, pl + ga);
        }
        // V tiles (hi/lo): 128 rows x 8 16B-chunks each (64 cols)
        for (int e = tid; e < 1024; e += 256) {
            int r = e >> 3, cc = e & 7;
            uint32_t so = (uint32_t)(r * LDT + cc * 8) * 2;
            size_t va = (size_t)(b * N_SEQ + j * 128 + r) * QKV_COLS + 2 * D_MODEL + h * 64 + cc * 8;
            cpa16(sVh + so, qh + va);
            cpa16(sVl + so, ql + va);
        }
        CP_COMMIT();
        CP_WAIT0();
        __syncthreads();

        #pragma unroll
        for (int kt = 0; kt < 8; kt++) {
            uint32_t ah[2][4], al[2][4], vh[2][4], vl[2][4];
            #pragma unroll
            for (int mt = 0; mt < 2; mt++) {
                uint32_t off = ((wm + mt * 16 + lrow) * LDP + kt * 16 + lcol) * 2;
                ldsm4(ah[mt], sPh + off);
                ldsm4(al[mt], sPl + off);
            }
            #pragma unroll
            for (int bt = 0; bt < 2; bt++) {
                uint32_t off = ((kt * 16 + lrow) * LDT + wn + bt * 16 + lcol) * 2;
                ldsm4t(vh[bt], sVh + off);
                ldsm4t(vl[bt], sVl + off);
            }
            #pragma unroll
            for (int mt = 0; mt < 2; mt++)
                #pragma unroll
                for (int nt = 0; nt < 4; nt++) {
                    const int bt = nt >> 1, s = (nt & 1) * 2;
                    mma16816(c[mt][nt], ah[mt], vh[bt][s], vh[bt][s + 1]);
                    mma16816(c[mt][nt], al[mt], vh[bt][s], vh[bt][s + 1]);
                    mma16816(c[mt][nt], ah[mt], vl[bt][s], vl[bt][s + 1]);
                }
        }
    }

    const int g = lane >> 2, tg = lane & 3;
    #pragma unroll
    for (int mt = 0; mt < 2; mt++)
        #pragma unroll
        for (int nt = 0; nt < 4; nt++) {
            const int q = i * 128 + wm + mt * 16 + g;
            const int d = wn + nt * 8 + tg * 2;
            __nv_bfloat16 h0, l0, h1, l1;
            bsplit(c[mt][nt][0], h0, l0);
            bsplit(c[mt][nt][1], h1, l1);
            __nv_bfloat162 hh; hh.x = h0; hh.y = h1;
            __nv_bfloat162 ll; ll.x = l0; ll.y = l1;
            *(__nv_bfloat162*)(ch + (size_t)(b * N_SEQ + q) * D_MODEL + h * 64 + d) = hh;
            *(__nv_bfloat162*)(cl + (size_t)(b * N_SEQ + q) * D_MODEL + h * 64 + d) = ll;
            bsplit(c[mt][nt][2], h0, l0);
            bsplit(c[mt][nt][3], h1, l1);
            hh.x = h0; hh.y = h1; ll.x = l0; ll.y = l1;
            *(__nv_bfloat162*)(ch + (size_t)(b * N_SEQ + q + 8) * D_MODEL + h * 64 + d) = hh;
            *(__nv_bfloat162*)(cl + (size_t)(b * N_SEQ + q + 8) * D_MODEL + h * 64 + d) = ll;
        }
}

// ---------------------------------------------------------------------------
extern "C" void kernel_launch(void* const* d_in, const int* in_sizes, int n_in,
                              void* d_out, int out_size)
{
    const float* x     = (const float*)d_in[0];
    const float* W_qkv = (const float*)d_in[1];
    const float* W_out = (const float*)d_in[2];
    float* out = (float*)d_out;

    float* attn_scratch;
    __nv_bfloat16 *php, *plp, *xh, *xl, *qkvh, *qkvl, *ch, *cl, *wqh, *wql, *woh, *wol;
    cudaGetSymbolAddress((void**)&attn_scratch, g_attn);
    cudaGetSymbolAddress((void**)&php, g_ph);
    cudaGetSymbolAddress((void**)&plp, g_pl);
    cudaGetSymbolAddress((void**)&xh, g_xh);
    cudaGetSymbolAddress((void**)&xl, g_xl);
    cudaGetSymbolAddress((void**)&qkvh, g_qkvh);
    cudaGetSymbolAddress((void**)&qkvl, g_qkvl);
    cudaGetSymbolAddress((void**)&ch, g_ch);
    cudaGetSymbolAddress((void**)&cl, g_cl);
    cudaGetSymbolAddress((void**)&wqh, g_wqh);
    cudaGetSymbolAddress((void**)&wql, g_wql);
    cudaGetSymbolAddress((void**)&woh, g_woh);
    cudaGetSymbolAddress((void**)&wol, g_wol);

    cudaFuncSetAttribute(gemm_mma<true>,  cudaFuncAttributeMaxDynamicSharedMemorySize, SMEM_G);
    cudaFuncSetAttribute(gemm_mma<false>, cudaFuncAttributeMaxDynamicSharedMemorySize, SMEM_G);
    cudaFuncSetAttribute(scores_mma,      cudaFuncAttributeMaxDynamicSharedMemorySize, SMEM_S);
    cudaFuncSetAttribute(pv_mma,          cudaFuncAttributeMaxDynamicSharedMemorySize, SMEM_PV);

    const long long out_elems  = (long long)B_SZ * N_SEQ * D_MODEL;
    const long long attn_elems = (long long)B_SZ * N_HEADS * N_SEQ * N_SEQ;
    const int write_attn = ((long long)out_size >= out_elems + attn_elems) ? 1 : 0;
    float* attn_buf = write_attn ? (out + out_elems) : attn_scratch;

    // 0) prep
    split_kernel<<<(M_ROWS * D_MODEL) / 1024, 256>>>(x, xh, xl);
    {
        dim3 grid(QKV_COLS / 32, D_MODEL / 32);
        wtrans_split<<<grid, dim3(32, 8)>>>(W_qkv, wqh, wql, D_MODEL, QKV_COLS);
    }
    {
        dim3 grid(D_MODEL / 32, D_MODEL / 32);
        wtrans_split<<<grid, dim3(32, 8)>>>(W_out, woh, wol, D_MODEL, D_MODEL);
    }

    // 1) QKV projection -> split bf16 qkv
    {
        dim3 grid(QKV_COLS / 128, M_ROWS / 128);
        gemm_mma<true><<<grid, 256, SMEM_G>>>(xh, xl, wqh, wql,
                                              nullptr, qkvh, qkvl, QKV_COLS, D_MODEL);
    }
    // 2a) raw scores
    {
        dim3 grid(NPAIR128, N_HEADS, B_SZ);
        scores_mma<<<grid, 256, SMEM_S>>>(qkvh, qkvl, attn_buf);
    }
    // 2b) one-pass softmax -> attn (fp32) + Ph/Pl (split bf16, causal span)
    {
        dim3 grid(N_SEQ, N_HEADS, B_SZ);
        softmax1p<<<grid, 256>>>(attn_buf, php, plp);
    }
    // 2c) P @ V -> split bf16 ctx (pure cp.async -> mma loop)
    {
        dim3 grid(NT128, N_HEADS, B_SZ);
        pv_mma<<<grid, 256, SMEM_PV>>>(php, plp, qkvh, qkvl, ch, cl);
    }
    // 3) output projection -> fp32 out
    {
        dim3 grid(D_MODEL / 128, M_ROWS / 128);
        gemm_mma<false><<<grid, 256, SMEM_G>>>(ch, cl, woh, wol,
                                               out, nullptr, nullptr, D_MODEL, D_MODEL);
    }
}

// round 14
// speedup vs baseline: 1.7265x; 1.0464x over previous
#include <cuda_runtime.h>
#include <cuda_bf16.h>
#include <math.h>
#include <stdint.h>

#define B_SZ    2
#define N_SEQ   2048
#define D_MODEL 1024
#define N_HEADS 16
#define D_HEAD  64
#define M_ROWS  (B_SZ * N_SEQ)        // 4096
#define QKV_COLS (3 * D_MODEL)        // 3072
#define NT128   (N_SEQ / 128)         // 16
#define NPAIR128 (NT128 * (NT128 + 1) / 2)  // 136

// ---------------- scratch ---------------------------------------------------
__device__ float g_attn[(size_t)B_SZ * N_HEADS * N_SEQ * N_SEQ];      // fallback
__device__ __nv_bfloat16 g_ph[(size_t)B_SZ * N_HEADS * N_SEQ * N_SEQ];
__device__ __nv_bfloat16 g_pl[(size_t)B_SZ * N_HEADS * N_SEQ * N_SEQ];
__device__ __nv_bfloat16 g_xh[(size_t)M_ROWS * D_MODEL];
__device__ __nv_bfloat16 g_xl[(size_t)M_ROWS * D_MODEL];
__device__ __nv_bfloat16 g_qkvh[(size_t)M_ROWS * QKV_COLS];
__device__ __nv_bfloat16 g_qkvl[(size_t)M_ROWS * QKV_COLS];
__device__ __nv_bfloat16 g_ch[(size_t)M_ROWS * D_MODEL];
__device__ __nv_bfloat16 g_cl[(size_t)M_ROWS * D_MODEL];
__device__ __nv_bfloat16 g_wqh[(size_t)QKV_COLS * D_MODEL];   // [N][K]
__device__ __nv_bfloat16 g_wql[(size_t)QKV_COLS * D_MODEL];
__device__ __nv_bfloat16 g_woh[(size_t)D_MODEL * D_MODEL];
__device__ __nv_bfloat16 g_wol[(size_t)D_MODEL * D_MODEL];

// ---------------- helpers ----------------------------------------------------
__device__ __forceinline__ uint32_t smem_u32(const void* p) {
    uint32_t a;
    asm("{ .reg .u64 t; cvta.to.shared.u64 t, %1; cvt.u32.u64 %0, t; }" : "=r"(a) : "l"(p));
    return a;
}
__device__ __forceinline__ void ldsm4(uint32_t* r, uint32_t a) {
    asm volatile("ldmatrix.sync.aligned.m8n8.x4.shared.b16 {%0,%1,%2,%3}, [%4];"
                 : "=r"(r[0]), "=r"(r[1]), "=r"(r[2]), "=r"(r[3]) : "r"(a));
}
__device__ __forceinline__ void ldsm4t(uint32_t* r, uint32_t a) {
    asm volatile("ldmatrix.sync.aligned.m8n8.x4.trans.shared.b16 {%0,%1,%2,%3}, [%4];"
                 : "=r"(r[0]), "=r"(r[1]), "=r"(r[2]), "=r"(r[3]) : "r"(a));
}
__device__ __forceinline__ void mma16816(float* c, const uint32_t* a, uint32_t b0, uint32_t b1) {
    asm volatile("mma.sync.aligned.m16n8k16.row.col.f32.bf16.bf16.f32 "
                 "{%0,%1,%2,%3}, {%4,%5,%6,%7}, {%8,%9}, {%0,%1,%2,%3};"
                 : "+f"(c[0]), "+f"(c[1]), "+f"(c[2]), "+f"(c[3])
                 : "r"(a[0]), "r"(a[1]), "r"(a[2]), "r"(a[3]), "r"(b0), "r"(b1));
}
__device__ __forceinline__ void bsplit(float v, __nv_bfloat16& h, __nv_bfloat16& l) {
    h = __float2bfloat16(v);
    l = __float2bfloat16(v - __bfloat162float(h));
}
__device__ __forceinline__ void cpa16(uint32_t saddr, const void* g) {
    asm volatile("cp.async.cg.shared.global [%0], [%1], 16;" :: "r"(saddr), "l"(g));
}
#define CP_COMMIT() asm volatile("cp.async.commit_group;" ::: "memory")
#define CP_WAIT0()  asm volatile("cp.async.wait_group 0;" ::: "memory")

// ---------------------------------------------------------------------------
// prep kernels
// ---------------------------------------------------------------------------
__global__ __launch_bounds__(256) void split_kernel(const float* __restrict__ s,
                                                    __nv_bfloat16* __restrict__ hi,
                                                    __nv_bfloat16* __restrict__ lo)
{
    size_t i = (size_t)blockIdx.x * 1024 + threadIdx.x * 4;
    float4 v = *(const float4*)&s[i];
    float vv[4] = {v.x, v.y, v.z, v.w};
    __nv_bfloat16 h[4], l[4];
    #pragma unroll
    for (int k = 0; k < 4; k++) bsplit(vv[k], h[k], l[k]);
    *(uint2*)&hi[i] = *(uint2*)h;
    *(uint2*)&lo[i] = *(uint2*)l;
}

// W[K][N] -> hi/lo[N][K]
__global__ void wtrans_split(const float* __restrict__ W,
                             __nv_bfloat16* __restrict__ hi,
                             __nv_bfloat16* __restrict__ lo, int K, int N)
{
    __shared__ float t[32][33];
    const int n0 = blockIdx.x * 32, k0 = blockIdx.y * 32;
    const int tx = threadIdx.x, ty = threadIdx.y;  // (32,8)
    for (int i = ty; i < 32; i += 8)
        t[i][tx] = W[(size_t)(k0 + i) * N + n0 + tx];
    __syncthreads();
    for (int i = ty; i < 32; i += 8) {
        float v = t[tx][i];
        __nv_bfloat16 h, l;
        bsplit(v, h, l);
        hi[(size_t)(n0 + i) * K + k0 + tx] = h;
        lo[(size_t)(n0 + i) * K + k0 + tx] = l;
    }
}

// ---------------------------------------------------------------------------
// GEMM: 128x64 tile, 128 threads (4 warps, 2m x 2n), cp.async loads, BK=64.
// Small smem (55.3KB) -> 4 CTAs/SM for cross-CTA latency hiding.
// ---------------------------------------------------------------------------
#define LDT 72
#define SMEM_G ((2 * 128 * LDT + 2 * 64 * LDT) * 2)   // 55296 B

template<bool SPLIT_OUT>
__global__ __launch_bounds__(128, 4) void gemm_mma(const __nv_bfloat16* __restrict__ ahi,
                                                   const __nv_bfloat16* __restrict__ alo,
                                                   const __nv_bfloat16* __restrict__ bhi,
                                                   const __nv_bfloat16* __restrict__ blo,
                                                   float* __restrict__ Cf,
                                                   __nv_bfloat16* __restrict__ Chi,
                                                   __nv_bfloat16* __restrict__ Clo,
                                                   int N, int K)
{
    extern __shared__ __nv_bfloat16 sm[];
    __nv_bfloat16* Ah = sm;                         // 128 x LDT
    __nv_bfloat16* Al = Ah + 128 * LDT;
    __nv_bfloat16* Bh = Al + 128 * LDT;             // 64 x LDT
    __nv_bfloat16* Bl = Bh + 64 * LDT;

    const int tid = threadIdx.x, lane = tid & 31, wid = tid >> 5;  // 0..3
    const int wm = (wid >> 1) * 64, wn = (wid & 1) * 32;
    const int row0 = blockIdx.y * 128, col0 = blockIdx.x * 64;
    const int lrow = lane & 15;
    const int lcol = (lane >> 4) * 8;

    const uint32_t sAh = smem_u32(Ah), sAl = smem_u32(Al);
    const uint32_t sBh = smem_u32(Bh), sBl = smem_u32(Bl);

    float c[4][4][4] = {};

    for (int k0 = 0; k0 < K; k0 += 64) {
        // A-pair: 128 rows x 8 chunks of 16B
        for (int e = tid; e < 1024; e += 128) {
            int r = e >> 3, cb = (e & 7) * 8;
            uint32_t so = (uint32_t)(r * LDT + cb) * 2;
            size_t ga = (size_t)(row0 + r) * K + k0 + cb;
            cpa16(sAh + so, ahi + ga);
            cpa16(sAl + so, alo + ga);
        }
        // B-pair: 64 rows x 8 chunks of 16B
        for (int e = tid; e < 512; e += 128) {
            int r = e >> 3, cb = (e & 7) * 8;
            uint32_t so = (uint32_t)(r * LDT + cb) * 2;
            size_t gb = (size_t)(col0 + r) * K + k0 + cb;
            cpa16(sBh + so, bhi + gb);
            cpa16(sBl + so, blo + gb);
        }
        CP_COMMIT();
        CP_WAIT0();
        __syncthreads();

        #pragma unroll
        for (int kt = 0; kt < 4; kt++) {
            uint32_t ah[4][4], al[4][4], bh[2][4], bl[2][4];
            #pragma unroll
            for (int mt = 0; mt < 4; mt++) {
                uint32_t off = ((wm + mt * 16 + lrow) * LDT + kt * 16 + lcol) * 2;
                ldsm4(ah[mt], sAh + off);
                ldsm4(al[mt], sAl + off);
            }
            #pragma unroll
            for (int bt = 0; bt < 2; bt++) {
                uint32_t off = ((wn + bt * 16 + lrow) * LDT + kt * 16 + lcol) * 2;
                ldsm4(bh[bt], sBh + off);
                ldsm4(bl[bt], sBl + off);
            }
            #pragma unroll
            for (int mt = 0; mt < 4; mt++)
                #pragma unroll
                for (int nt = 0; nt < 4; nt++) {
                    const int bt = nt >> 1, s = nt & 1;
                    mma16816(c[mt][nt], ah[mt], bh[bt][s], bh[bt][s + 2]);
                    mma16816(c[mt][nt], al[mt], bh[bt][s], bh[bt][s + 2]);
                    mma16816(c[mt][nt], ah[mt], bl[bt][s], bl[bt][s + 2]);
                }
        }
        __syncthreads();
    }

    const int g = lane >> 2, tg = lane & 3;
    #pragma unroll
    for (int mt = 0; mt < 4; mt++)
        #pragma unroll
        for (int nt = 0; nt < 4; nt++) {
            const int row = row0 + wm + mt * 16 + g;
            const int col = col0 + wn + nt * 8 + tg * 2;
            if (SPLIT_OUT) {
                __nv_bfloat16 h0, l0, h1, l1;
                bsplit(c[mt][nt][0], h0, l0);
                bsplit(c[mt][nt][1], h1, l1);
                __nv_bfloat162 hh; hh.x = h0; hh.y = h1;
                __nv_bfloat162 ll; ll.x = l0; ll.y = l1;
                *(__nv_bfloat162*)(Chi + (size_t)row * N + col) = hh;
                *(__nv_bfloat162*)(Clo + (size_t)row * N + col) = ll;
                bsplit(c[mt][nt][2], h0, l0);
                bsplit(c[mt][nt][3], h1, l1);
                hh.x = h0; hh.y = h1; ll.x = l0; ll.y = l1;
                *(__nv_bfloat162*)(Chi + (size_t)(row + 8) * N + col) = hh;
                *(__nv_bfloat162*)(Clo + (size_t)(row + 8) * N + col) = ll;
            } else {
                *(float2*)(Cf + (size_t)row * N + col) = make_float2(c[mt][nt][0], c[mt][nt][1]);
                *(float2*)(Cf + (size_t)(row + 8) * N + col) = make_float2(c[mt][nt][2], c[mt][nt][3]);
            }
        }
}

// ---------------------------------------------------------------------------
// Scores: S = (Q.K^T)/8 for lower-triangular 128x128 tile pairs. K-dim = 64.
// ---------------------------------------------------------------------------
#define SMEM_S (4 * 128 * LDT * 2)

__global__ __launch_bounds__(256, 2) void scores_mma(const __nv_bfloat16* __restrict__ qh,
                                                     const __nv_bfloat16* __restrict__ ql,
                                                     float* __restrict__ attn)
{
    const int t = blockIdx.x, h = blockIdx.y, b = blockIdx.z;
    int i = 0;
    while ((i + 1) * (i + 2) / 2 <= t) i++;
    const int j = t - i * (i + 1) / 2;

    extern __shared__ __nv_bfloat16 sm[];
    const uint32_t smb = smem_u32(sm);
    const uint32_t sQh = smb;
    const uint32_t sQl = smb + 128*LDT*2;
    const uint32_t sKh = smb + 2*128*LDT*2;
    const uint32_t sKl = smb + 3*128*LDT*2;

    const int tid = threadIdx.x, lane = tid & 31, wid = tid >> 5;
    const int wm = (wid >> 2) * 64, wn = (wid & 3) * 32;
    const int lrow = lane & 15, lcol = (lane >> 4) * 8;

    {
        const int r_ = tid >> 3, cb_ = (tid & 7) * 8;
        #pragma unroll
        for (int rr = 0; rr < 4; rr++) {
            int r = r_ + rr * 32;
            uint32_t so = (uint32_t)(r * LDT + cb_) * 2;
            size_t qa = (size_t)(b * N_SEQ + i * 128 + r) * QKV_COLS + h * 64 + cb_;
            size_t ka = (size_t)(b * N_SEQ + j * 128 + r) * QKV_COLS + D_MODEL + h * 64 + cb_;
            cpa16(sQh + so, qh + qa);
            cpa16(sQl + so, ql + qa);
            cpa16(sKh + so, qh + ka);
            cpa16(sKl + so, ql + ka);
        }
        CP_COMMIT();
        CP_WAIT0();
    }
    __syncthreads();

    float c[4][4][4] = {};
    #pragma unroll
    for (int kt = 0; kt < 4; kt++) {
        uint32_t ah[4][4], al[4][4], bh[2][4], bl[2][4];
        #pragma unroll
        for (int mt = 0; mt < 4; mt++) {
            uint32_t off = ((wm + mt * 16 + lrow) * LDT + kt * 16 + lcol) * 2;
            ldsm4(ah[mt], sQh + off);
            ldsm4(al[mt], sQl + off);
        }
        #pragma unroll
        for (int bt = 0; bt < 2; bt++) {
            uint32_t off = ((wn + bt * 16 + lrow) * LDT + kt * 16 + lcol) * 2;
            ldsm4(bh[bt], sKh + off);
            ldsm4(bl[bt], sKl + off);
        }
        #pragma unroll
        for (int mt = 0; mt < 4; mt++)
            #pragma unroll
            for (int nt = 0; nt < 4; nt++) {
                const int bt = nt >> 1, s = nt & 1;
                mma16816(c[mt][nt], ah[mt], bh[bt][s], bh[bt][s + 2]);
                mma16816(c[mt][nt], al[mt], bh[bt][s], bh[bt][s + 2]);
                mma16816(c[mt][nt], ah[mt], bl[bt][s], bl[bt][s + 2]);
            }
    }

    float* base = attn + ((size_t)(b * N_HEADS + h)) * N_SEQ * N_SEQ;
    const int g = lane >> 2, tg = lane & 3;
    #pragma unroll
    for (int mt = 0; mt < 4; mt++)
        #pragma unroll
        for (int nt = 0; nt < 4; nt++) {
            const int q = i * 128 + wm + mt * 16 + g;
            const int col = j * 128 + wn + nt * 8 + tg * 2;
            *(float2*)(base + (size_t)q * N_SEQ + col) =
                make_float2(c[mt][nt][0] * 0.125f, c[mt][nt][1] * 0.125f);
            *(float2*)(base + (size_t)(q + 8) * N_SEQ + col) =
                make_float2(c[mt][nt][2] * 0.125f, c[mt][nt][3] * 0.125f);
        }
}

// ---------------------------------------------------------------------------
// One-pass softmax; also emits split-bf16 P (Ph/Pl) for the causal tile span.
// ---------------------------------------------------------------------------
__global__ __launch_bounds__(256) void softmax1p(float* __restrict__ attn,
                                                 __nv_bfloat16* __restrict__ ph,
                                                 __nv_bfloat16* __restrict__ pl)
{
    const int n = blockIdx.x, h = blockIdx.y, b = blockIdx.z;
    const int tid = threadIdx.x;
    const size_t rowbase = ((size_t)(b * N_HEADS + h) * N_SEQ + n) * N_SEQ;
    float* row = attn + rowbase;

    __shared__ float red[256];
    const int P = n + 1, n4 = P >> 2, tail = P & 3;
    const int cover4 = (((P + 127) >> 7) << 5);   // float4 groups covering causal tiles

    float4 v[2];
    int cnt = 0;
    float lmax = -INFINITY;
    #pragma unroll
    for (int k = 0; k < 2; k++) {
        int m4 = tid + k * 256;
        if (m4 < n4) {
            float4 x = *(const float4*)&row[m4 * 4];
            v[cnt++] = x;
            lmax = fmaxf(lmax, fmaxf(fmaxf(x.x, x.y), fmaxf(x.z, x.w)));
        }
    }
    float tv = 0.f;
    const bool hasT = (tid < tail);
    if (hasT) { tv = row[n4 * 4 + tid]; lmax = fmaxf(lmax, tv); }

    red[tid] = lmax;
    __syncthreads();
    #pragma unroll
    for (int s = 128; s > 0; s >>= 1) {
        if (tid < s) red[tid] = fmaxf(red[tid], red[tid + s]);
        __syncthreads();
    }
    const float mx = red[0];
    __syncthreads();

    float ls = 0.f;
    for (int k = 0; k < cnt; k++)
        ls += __expf(v[k].x - mx) + __expf(v[k].y - mx) +
              __expf(v[k].z - mx) + __expf(v[k].w - mx);
    if (hasT) ls += __expf(tv - mx);
    red[tid] = ls;
    __syncthreads();
    #pragma unroll
    for (int s = 128; s > 0; s >>= 1) {
        if (tid < s) red[tid] += red[tid + s];
        __syncthreads();
    }
    const float inv = 1.f / red[0];

    cnt = 0;
    #pragma unroll
    for (int k = 0; k < 2; k++) {
        int m4 = tid + k * 256;
        float4 o;
        if (m4 < n4) {
            float4 x = v[cnt++];
            o.x = __expf(x.x - mx) * inv;
            o.y = __expf(x.y - mx) * inv;
            o.z = __expf(x.z - mx) * inv;
            o.w = __expf(x.w - mx) * inv;
        } else if (m4 == n4 && tail) {
            float4 x = *(const float4*)&row[m4 * 4];
            float xx[4] = {x.x, x.y, x.z, x.w};
            float oo[4];
            #pragma unroll
            for (int q = 0; q < 4; q++)
                oo[q] = (m4 * 4 + q < P) ? __expf(xx[q] - mx) * inv : 0.f;
            o = make_float4(oo[0], oo[1], oo[2], oo[3]);
        } else {
            o = make_float4(0.f, 0.f, 0.f, 0.f);
        }
        *(float4*)&row[m4 * 4] = o;

        if (m4 < cover4) {
            float oo[4] = {o.x, o.y, o.z, o.w};
            __nv_bfloat16 hh[4], ll[4];
            #pragma unroll
            for (int q = 0; q < 4; q++) bsplit(oo[q], hh[q], ll[q]);
            *(uint2*)&ph[rowbase + m4 * 4] = *(uint2*)hh;
            *(uint2*)&pl[rowbase + m4 * 4] = *(uint2*)ll;
        }
    }
}

// ---------------------------------------------------------------------------
// PV: ctx = P @ V; all operand tiles (Ph,Pl,Vh,Vl) pulled via cp.async.
// ---------------------------------------------------------------------------
#define LDP 136
#define SMEM_PV ((2 * 128 * LDP + 2 * 128 * LDT) * 2)   // 106496 B

__global__ __launch_bounds__(256) void pv_mma(const __nv_bfloat16* __restrict__ ph,
                                              const __nv_bfloat16* __restrict__ pl,
                                              const __nv_bfloat16* __restrict__ qh,
                                              const __nv_bfloat16* __restrict__ ql,
                                              __nv_bfloat16* __restrict__ ch,
                                              __nv_bfloat16* __restrict__ cl)
{
    const int i = NT128 - 1 - blockIdx.x;   // heavy first
    const int h = blockIdx.y, b = blockIdx.z;

    extern __shared__ __nv_bfloat16 sm[];
    __nv_bfloat16* Ph = sm;
    __nv_bfloat16* Pl = Ph + 128 * LDP;
    __nv_bfloat16* Vh = Pl + 128 * LDP;
    __nv_bfloat16* Vl = Vh + 128 * LDT;

    const int tid = threadIdx.x, lane = tid & 31, wid = tid >> 5;
    const int wm = (wid >> 1) * 32, wn = (wid & 1) * 32;
    const int lrow = lane & 15, lcol = (lane >> 4) * 8;

    const uint32_t sPh = smem_u32(Ph), sPl = smem_u32(Pl);
    const uint32_t sVh = smem_u32(Vh), sVl = smem_u32(Vl);

    const size_t pbase = ((size_t)(b * N_HEADS + h)) * N_SEQ * N_SEQ
                       + (size_t)i * 128 * N_SEQ;
    float c[2][4][4] = {};

    for (int j = 0; j <= i; j++) {
        if (j) __syncthreads();
        // P tiles (hi/lo): 128 rows x 16 16B-chunks each
        for (int e = tid; e < 2048; e += 256) {
            int r = e >> 4, cc = e & 15;
            uint32_t so = (uint32_t)(r * LDP + cc * 8) * 2;
            size_t ga = pbase + (size_t)r * N_SEQ + j * 128 + cc * 8;
            cpa16(sPh + so, ph + ga);
            cpa16(sPl + so, pl + ga);
        }
        // V tiles (hi/lo): 128 rows x 8 16B-chunks each (64 cols)
        for (int e = tid; e < 1024; e += 256) {
            int r = e >> 3, cc = e & 7;
            uint32_t so = (uint32_t)(r * LDT + cc * 8) * 2;
            size_t va = (size_t)(b * N_SEQ + j * 128 + r) * QKV_COLS + 2 * D_MODEL + h * 64 + cc * 8;
            cpa16(sVh + so, qh + va);
            cpa16(sVl + so, ql + va);
        }
        CP_COMMIT();
        CP_WAIT0();
        __syncthreads();

        #pragma unroll
        for (int kt = 0; kt < 8; kt++) {
            uint32_t ah[2][4], al[2][4], vh[2][4], vl[2][4];
            #pragma unroll
            for (int mt = 0; mt < 2; mt++) {
                uint32_t off = ((wm + mt * 16 + lrow) * LDP + kt * 16 + lcol) * 2;
                ldsm4(ah[mt], sPh + off);
                ldsm4(al[mt], sPl + off);
            }
            #pragma unroll
            for (int bt = 0; bt < 2; bt++) {
                uint32_t off = ((kt * 16 + lrow) * LDT + wn + bt * 16 + lcol) * 2;
                ldsm4t(vh[bt], sVh + off);
                ldsm4t(vl[bt], sVl + off);
            }
            #pragma unroll
            for (int mt = 0; mt < 2; mt++)
                #pragma unroll
                for (int nt = 0; nt < 4; nt++) {
                    const int bt = nt >> 1, s = (nt & 1) * 2;
                    mma16816(c[mt][nt], ah[mt], vh[bt][s], vh[bt][s + 1]);
                    mma16816(c[mt][nt], al[mt], vh[bt][s], vh[bt][s + 1]);
                    mma16816(c[mt][nt], ah[mt], vl[bt][s], vl[bt][s + 1]);
                }
        }
    }

    const int g = lane >> 2, tg = lane & 3;
    #pragma unroll
    for (int mt = 0; mt < 2; mt++)
        #pragma unroll
        for (int nt = 0; nt < 4; nt++) {
            const int q = i * 128 + wm + mt * 16 + g;
            const int d = wn + nt * 8 + tg * 2;
            __nv_bfloat16 h0, l0, h1, l1;
            bsplit(c[mt][nt][0], h0, l0);
            bsplit(c[mt][nt][1], h1, l1);
            __nv_bfloat162 hh; hh.x = h0; hh.y = h1;
            __nv_bfloat162 ll; ll.x = l0; ll.y = l1;
            *(__nv_bfloat162*)(ch + (size_t)(b * N_SEQ + q) * D_MODEL + h * 64 + d) = hh;
            *(__nv_bfloat162*)(cl + (size_t)(b * N_SEQ + q) * D_MODEL + h * 64 + d) = ll;
            bsplit(c[mt][nt][2], h0, l0);
            bsplit(c[mt][nt][3], h1, l1);
            hh.x = h0; hh.y = h1; ll.x = l0; ll.y = l1;
            *(__nv_bfloat162*)(ch + (size_t)(b * N_SEQ + q + 8) * D_MODEL + h * 64 + d) = hh;
            *(__nv_bfloat162*)(cl + (size_t)(b * N_SEQ + q + 8) * D_MODEL + h * 64 + d) = ll;
        }
}

// ---------------------------------------------------------------------------
extern "C" void kernel_launch(void* const* d_in, const int* in_sizes, int n_in,
                              void* d_out, int out_size)
{
    const float* x     = (const float*)d_in[0];
    const float* W_qkv = (const float*)d_in[1];
    const float* W_out = (const float*)d_in[2];
    float* out = (float*)d_out;

    float* attn_scratch;
    __nv_bfloat16 *php, *plp, *xh, *xl, *qkvh, *qkvl, *ch, *cl, *wqh, *wql, *woh, *wol;
    cudaGetSymbolAddress((void**)&attn_scratch, g_attn);
    cudaGetSymbolAddress((void**)&php, g_ph);
    cudaGetSymbolAddress((void**)&plp, g_pl);
    cudaGetSymbolAddress((void**)&xh, g_xh);
    cudaGetSymbolAddress((void**)&xl, g_xl);
    cudaGetSymbolAddress((void**)&qkvh, g_qkvh);
    cudaGetSymbolAddress((void**)&qkvl, g_qkvl);
    cudaGetSymbolAddress((void**)&ch, g_ch);
    cudaGetSymbolAddress((void**)&cl, g_cl);
    cudaGetSymbolAddress((void**)&wqh, g_wqh);
    cudaGetSymbolAddress((void**)&wql, g_wql);
    cudaGetSymbolAddress((void**)&woh, g_woh);
    cudaGetSymbolAddress((void**)&wol, g_wol);

    cudaFuncSetAttribute(gemm_mma<true>,  cudaFuncAttributeMaxDynamicSharedMemorySize, SMEM_G);
    cudaFuncSetAttribute(gemm_mma<false>, cudaFuncAttributeMaxDynamicSharedMemorySize, SMEM_G);
    cudaFuncSetAttribute(scores_mma,      cudaFuncAttributeMaxDynamicSharedMemorySize, SMEM_S);
    cudaFuncSetAttribute(pv_mma,          cudaFuncAttributeMaxDynamicSharedMemorySize, SMEM_PV);

    const long long out_elems  = (long long)B_SZ * N_SEQ * D_MODEL;
    const long long attn_elems = (long long)B_SZ * N_HEADS * N_SEQ * N_SEQ;
    const int write_attn = ((long long)out_size >= out_elems + attn_elems) ? 1 : 0;
    float* attn_buf = write_attn ? (out + out_elems) : attn_scratch;

    // 0) prep
    split_kernel<<<(M_ROWS * D_MODEL) / 1024, 256>>>(x, xh, xl);
    {
        dim3 grid(QKV_COLS / 32, D_MODEL / 32);
        wtrans_split<<<grid, dim3(32, 8)>>>(W_qkv, wqh, wql, D_MODEL, QKV_COLS);
    }
    {
        dim3 grid(D_MODEL / 32, D_MODEL / 32);
        wtrans_split<<<grid, dim3(32, 8)>>>(W_out, woh, wol, D_MODEL, D_MODEL);
    }

    // 1) QKV projection -> split bf16 qkv
    {
        dim3 grid(QKV_COLS / 64, M_ROWS / 128);
        gemm_mma<true><<<grid, 128, SMEM_G>>>(xh, xl, wqh, wql,
                                              nullptr, qkvh, qkvl, QKV_COLS, D_MODEL);
    }
    // 2a) raw scores
    {
        dim3 grid(NPAIR128, N_HEADS, B_SZ);
        scores_mma<<<grid, 256, SMEM_S>>>(qkvh, qkvl, attn_buf);
    }
    // 2b) one-pass softmax -> attn (fp32) + Ph/Pl (split bf16, causal span)
    {
        dim3 grid(N_SEQ, N_HEADS, B_SZ);
        softmax1p<<<grid, 256>>>(attn_buf, php, plp);
    }
    // 2c) P @ V -> split bf16 ctx (pure cp.async -> mma loop)
    {
        dim3 grid(NT128, N_HEADS, B_SZ);
        pv_mma<<<grid, 256, SMEM_PV>>>(php, plp, qkvh, qkvl, ch, cl);
    }
    // 3) output projection -> fp32 out
    {
        dim3 grid(D_MODEL / 64, M_ROWS / 128);
        gemm_mma<false><<<grid, 128, SMEM_G>>>(ch, cl, woh, wol,
                                               out, nullptr, nullptr, D_MODEL, D_MODEL);
    }
}

// round 16
// speedup vs baseline: 1.7405x; 1.0081x over previous
#include <cuda_runtime.h>
#include <cuda_bf16.h>
#include <math.h>
#include <stdint.h>

#define B_SZ    2
#define N_SEQ   2048
#define D_MODEL 1024
#define N_HEADS 16
#define D_HEAD  64
#define M_ROWS  (B_SZ * N_SEQ)        // 4096
#define QKV_COLS (3 * D_MODEL)        // 3072
#define NT128   (N_SEQ / 128)         // 16
#define NPAIR128 (NT128 * (NT128 + 1) / 2)  // 136

// ---------------- scratch ---------------------------------------------------
__device__ float g_attn[(size_t)B_SZ * N_HEADS * N_SEQ * N_SEQ];      // fallback
__device__ __nv_bfloat16 g_ph[(size_t)B_SZ * N_HEADS * N_SEQ * N_SEQ];
__device__ __nv_bfloat16 g_pl[(size_t)B_SZ * N_HEADS * N_SEQ * N_SEQ];
__device__ __nv_bfloat16 g_xh[(size_t)M_ROWS * D_MODEL];
__device__ __nv_bfloat16 g_xl[(size_t)M_ROWS * D_MODEL];
__device__ __nv_bfloat16 g_qkvh[(size_t)M_ROWS * QKV_COLS];
__device__ __nv_bfloat16 g_qkvl[(size_t)M_ROWS * QKV_COLS];
__device__ __nv_bfloat16 g_ch[(size_t)M_ROWS * D_MODEL];
__device__ __nv_bfloat16 g_cl[(size_t)M_ROWS * D_MODEL];
__device__ __nv_bfloat16 g_wqh[(size_t)QKV_COLS * D_MODEL];   // [N][K]
__device__ __nv_bfloat16 g_wql[(size_t)QKV_COLS * D_MODEL];
__device__ __nv_bfloat16 g_woh[(size_t)D_MODEL * D_MODEL];
__device__ __nv_bfloat16 g_wol[(size_t)D_MODEL * D_MODEL];

// ---------------- helpers ----------------------------------------------------
__device__ __forceinline__ uint32_t smem_u32(const void* p) {
    uint32_t a;
    asm("{ .reg .u64 t; cvta.to.shared.u64 t, %1; cvt.u32.u64 %0, t; }" : "=r"(a) : "l"(p));
    return a;
}
__device__ __forceinline__ void ldsm4(uint32_t* r, uint32_t a) {
    asm volatile("ldmatrix.sync.aligned.m8n8.x4.shared.b16 {%0,%1,%2,%3}, [%4];"
                 : "=r"(r[0]), "=r"(r[1]), "=r"(r[2]), "=r"(r[3]) : "r"(a));
}
__device__ __forceinline__ void ldsm4t(uint32_t* r, uint32_t a) {
    asm volatile("ldmatrix.sync.aligned.m8n8.x4.trans.shared.b16 {%0,%1,%2,%3}, [%4];"
                 : "=r"(r[0]), "=r"(r[1]), "=r"(r[2]), "=r"(r[3]) : "r"(a));
}
__device__ __forceinline__ void mma16816(float* c, const uint32_t* a, uint32_t b0, uint32_t b1) {
    asm volatile("mma.sync.aligned.m16n8k16.row.col.f32.bf16.bf16.f32 "
                 "{%0,%1,%2,%3}, {%4,%5,%6,%7}, {%8,%9}, {%0,%1,%2,%3};"
                 : "+f"(c[0]), "+f"(c[1]), "+f"(c[2]), "+f"(c[3])
                 : "r"(a[0]), "r"(a[1]), "r"(a[2]), "r"(a[3]), "r"(b0), "r"(b1));
}
__device__ __forceinline__ void bsplit(float v, __nv_bfloat16& h, __nv_bfloat16& l) {
    h = __float2bfloat16(v);
    l = __float2bfloat16(v - __bfloat162float(h));
}
__device__ __forceinline__ void cpa16(uint32_t saddr, const void* g) {
    asm volatile("cp.async.cg.shared.global [%0], [%1], 16;" :: "r"(saddr), "l"(g));
}
#define CP_COMMIT() asm volatile("cp.async.commit_group;" ::: "memory")
#define CP_WAIT0()  asm volatile("cp.async.wait_group 0;" ::: "memory")

// ---------------------------------------------------------------------------
// prep kernels
// ---------------------------------------------------------------------------
__global__ __launch_bounds__(256) void split_kernel(const float* __restrict__ s,
                                                    __nv_bfloat16* __restrict__ hi,
                                                    __nv_bfloat16* __restrict__ lo)
{
    size_t i = (size_t)blockIdx.x * 1024 + threadIdx.x * 4;
    float4 v = *(const float4*)&s[i];
    float vv[4] = {v.x, v.y, v.z, v.w};
    __nv_bfloat16 h[4], l[4];
    #pragma unroll
    for (int k = 0; k < 4; k++) bsplit(vv[k], h[k], l[k]);
    *(uint2*)&hi[i] = *(uint2*)h;
    *(uint2*)&lo[i] = *(uint2*)l;
}

// W[K][N] -> hi/lo[N][K]
__global__ void wtrans_split(const float* __restrict__ W,
                             __nv_bfloat16* __restrict__ hi,
                             __nv_bfloat16* __restrict__ lo, int K, int N)
{
    __shared__ float t[32][33];
    const int n0 = blockIdx.x * 32, k0 = blockIdx.y * 32;
    const int tx = threadIdx.x, ty = threadIdx.y;  // (32,8)
    for (int i = ty; i < 32; i += 8)
        t[i][tx] = W[(size_t)(k0 + i) * N + n0 + tx];
    __syncthreads();
    for (int i = ty; i < 32; i += 8) {
        float v = t[tx][i];
        __nv_bfloat16 h, l;
        bsplit(v, h, l);
        hi[(size_t)(n0 + i) * K + k0 + tx] = h;
        lo[(size_t)(n0 + i) * K + k0 + tx] = l;
    }
}

// ---------------------------------------------------------------------------
// GEMM: 128x64 tile, 128 threads (4 warps, 2m x 2n), cp.async loads, BK=64.
// Inner loop staged term-by-term to keep live registers under the 128 cap
// (hh -> lh -> hl), avoiding local-memory spills at 4 CTAs/SM.
// ---------------------------------------------------------------------------
#define LDT 72
#define SMEM_G ((2 * 128 * LDT + 2 * 64 * LDT) * 2)   // 55296 B

template<bool SPLIT_OUT>
__global__ __launch_bounds__(128, 4) void gemm_mma(const __nv_bfloat16* __restrict__ ahi,
                                                   const __nv_bfloat16* __restrict__ alo,
                                                   const __nv_bfloat16* __restrict__ bhi,
                                                   const __nv_bfloat16* __restrict__ blo,
                                                   float* __restrict__ Cf,
                                                   __nv_bfloat16* __restrict__ Chi,
                                                   __nv_bfloat16* __restrict__ Clo,
                                                   int N, int K)
{
    extern __shared__ __nv_bfloat16 sm[];
    __nv_bfloat16* Ah = sm;                         // 128 x LDT
    __nv_bfloat16* Al = Ah + 128 * LDT;
    __nv_bfloat16* Bh = Al + 128 * LDT;             // 64 x LDT
    __nv_bfloat16* Bl = Bh + 64 * LDT;

    const int tid = threadIdx.x, lane = tid & 31, wid = tid >> 5;  // 0..3
    const int wm = (wid >> 1) * 64, wn = (wid & 1) * 32;
    const int row0 = blockIdx.y * 128, col0 = blockIdx.x * 64;
    const int lrow = lane & 15;
    const int lcol = (lane >> 4) * 8;

    const uint32_t sAh = smem_u32(Ah), sAl = smem_u32(Al);
    const uint32_t sBh = smem_u32(Bh), sBl = smem_u32(Bl);

    float c[4][4][4] = {};

    for (int k0 = 0; k0 < K; k0 += 64) {
        // A-pair: 128 rows x 8 chunks of 16B
        for (int e = tid; e < 1024; e += 128) {
            int r = e >> 3, cb = (e & 7) * 8;
            uint32_t so = (uint32_t)(r * LDT + cb) * 2;
            size_t ga = (size_t)(row0 + r) * K + k0 + cb;
            cpa16(sAh + so, ahi + ga);
            cpa16(sAl + so, alo + ga);
        }
        // B-pair: 64 rows x 8 chunks of 16B
        for (int e = tid; e < 512; e += 128) {
            int r = e >> 3, cb = (e & 7) * 8;
            uint32_t so = (uint32_t)(r * LDT + cb) * 2;
            size_t gb = (size_t)(col0 + r) * K + k0 + cb;
            cpa16(sBh + so, bhi + gb);
            cpa16(sBl + so, blo + gb);
        }
        CP_COMMIT();
        CP_WAIT0();
        __syncthreads();

        #pragma unroll
        for (int kt = 0; kt < 4; kt++) {
            // --- term 1: ah x bh ------------------------------------------
            uint32_t ah[4][4], bh[2][4];
            #pragma unroll
            for (int mt = 0; mt < 4; mt++) {
                uint32_t off = ((wm + mt * 16 + lrow) * LDT + kt * 16 + lcol) * 2;
                ldsm4(ah[mt], sAh + off);
            }
            #pragma unroll
            for (int bt = 0; bt < 2; bt++) {
                uint32_t off = ((wn + bt * 16 + lrow) * LDT + kt * 16 + lcol) * 2;
                ldsm4(bh[bt], sBh + off);
            }
            #pragma unroll
            for (int mt = 0; mt < 4; mt++)
                #pragma unroll
                for (int nt = 0; nt < 4; nt++) {
                    const int bt = nt >> 1, s = nt & 1;
                    mma16816(c[mt][nt], ah[mt], bh[bt][s], bh[bt][s + 2]);
                }
            // --- term 2: al x bh (al scoped; dead after) ------------------
            {
                uint32_t al[4][4];
                #pragma unroll
                for (int mt = 0; mt < 4; mt++) {
                    uint32_t off = ((wm + mt * 16 + lrow) * LDT + kt * 16 + lcol) * 2;
                    ldsm4(al[mt], sAl + off);
                }
                #pragma unroll
                for (int mt = 0; mt < 4; mt++)
                    #pragma unroll
                    for (int nt = 0; nt < 4; nt++) {
                        const int bt = nt >> 1, s = nt & 1;
                        mma16816(c[mt][nt], al[mt], bh[bt][s], bh[bt][s + 2]);
                    }
            }
            // --- term 3: ah x bl (bl scoped) ------------------------------
            {
                uint32_t bl[2][4];
                #pragma unroll
                for (int bt = 0; bt < 2; bt++) {
                    uint32_t off = ((wn + bt * 16 + lrow) * LDT + kt * 16 + lcol) * 2;
                    ldsm4(bl[bt], sBl + off);
                }
                #pragma unroll
                for (int mt = 0; mt < 4; mt++)
                    #pragma unroll
                    for (int nt = 0; nt < 4; nt++) {
                        const int bt = nt >> 1, s = nt & 1;
                        mma16816(c[mt][nt], ah[mt], bl[bt][s], bl[bt][s + 2]);
                    }
            }
        }
        __syncthreads();
    }

    const int g = lane >> 2, tg = lane & 3;
    #pragma unroll
    for (int mt = 0; mt < 4; mt++)
        #pragma unroll
        for (int nt = 0; nt < 4; nt++) {
            const int row = row0 + wm + mt * 16 + g;
            const int col = col0 + wn + nt * 8 + tg * 2;
            if (SPLIT_OUT) {
                __nv_bfloat16 h0, l0, h1, l1;
                bsplit(c[mt][nt][0], h0, l0);
                bsplit(c[mt][nt][1], h1, l1);
                __nv_bfloat162 hh; hh.x = h0; hh.y = h1;
                __nv_bfloat162 ll; ll.x = l0; ll.y = l1;
                *(__nv_bfloat162*)(Chi + (size_t)row * N + col) = hh;
                *(__nv_bfloat162*)(Clo + (size_t)row * N + col) = ll;
                bsplit(c[mt][nt][2], h0, l0);
                bsplit(c[mt][nt][3], h1, l1);
                hh.x = h0; hh.y = h1; ll.x = l0; ll.y = l1;
                *(__nv_bfloat162*)(Chi + (size_t)(row + 8) * N + col) = hh;
                *(__nv_bfloat162*)(Clo + (size_t)(row + 8) * N + col) = ll;
            } else {
                *(float2*)(Cf + (size_t)row * N + col) = make_float2(c[mt][nt][0], c[mt][nt][1]);
                *(float2*)(Cf + (size_t)(row + 8) * N + col) = make_float2(c[mt][nt][2], c[mt][nt][3]);
            }
        }
}

// ---------------------------------------------------------------------------
// Scores: S = (Q.K^T)/8 for lower-triangular 128x128 tile pairs. K-dim = 64.
// ---------------------------------------------------------------------------
#define SMEM_S (4 * 128 * LDT * 2)

__global__ __launch_bounds__(256, 2) void scores_mma(const __nv_bfloat16* __restrict__ qh,
                                                     const __nv_bfloat16* __restrict__ ql,
                                                     float* __restrict__ attn)
{
    const int t = blockIdx.x, h = blockIdx.y, b = blockIdx.z;
    int i = 0;
    while ((i + 1) * (i + 2) / 2 <= t) i++;
    const int j = t - i * (i + 1) / 2;

    extern __shared__ __nv_bfloat16 sm[];
    const uint32_t smb = smem_u32(sm);
    const uint32_t sQh = smb;
    const uint32_t sQl = smb + 128*LDT*2;
    const uint32_t sKh = smb + 2*128*LDT*2;
    const uint32_t sKl = smb + 3*128*LDT*2;

    const int tid = threadIdx.x, lane = tid & 31, wid = tid >> 5;
    const int wm = (wid >> 2) * 64, wn = (wid & 3) * 32;
    const int lrow = lane & 15, lcol = (lane >> 4) * 8;

    {
        const int r_ = tid >> 3, cb_ = (tid & 7) * 8;
        #pragma unroll
        for (int rr = 0; rr < 4; rr++) {
            int r = r_ + rr * 32;
            uint32_t so = (uint32_t)(r * LDT + cb_) * 2;
            size_t qa = (size_t)(b * N_SEQ + i * 128 + r) * QKV_COLS + h * 64 + cb_;
            size_t ka = (size_t)(b * N_SEQ + j * 128 + r) * QKV_COLS + D_MODEL + h * 64 + cb_;
            cpa16(sQh + so, qh + qa);
            cpa16(sQl + so, ql + qa);
            cpa16(sKh + so, qh + ka);
            cpa16(sKl + so, ql + ka);
        }
        CP_COMMIT();
        CP_WAIT0();
    }
    __syncthreads();

    float c[4][4][4] = {};
    #pragma unroll
    for (int kt = 0; kt < 4; kt++) {
        uint32_t ah[4][4], al[4][4], bh[2][4], bl[2][4];
        #pragma unroll
        for (int mt = 0; mt < 4; mt++) {
            uint32_t off = ((wm + mt * 16 + lrow) * LDT + kt * 16 + lcol) * 2;
            ldsm4(ah[mt], sQh + off);
            ldsm4(al[mt], sQl + off);
        }
        #pragma unroll
        for (int bt = 0; bt < 2; bt++) {
            uint32_t off = ((wn + bt * 16 + lrow) * LDT + kt * 16 + lcol) * 2;
            ldsm4(bh[bt], sKh + off);
            ldsm4(bl[bt], sKl + off);
        }
        #pragma unroll
        for (int mt = 0; mt < 4; mt++)
            #pragma unroll
            for (int nt = 0; nt < 4; nt++) {
                const int bt = nt >> 1, s = nt & 1;
                mma16816(c[mt][nt], ah[mt], bh[bt][s], bh[bt][s + 2]);
                mma16816(c[mt][nt], al[mt], bh[bt][s], bh[bt][s + 2]);
                mma16816(c[mt][nt], ah[mt], bl[bt][s], bl[bt][s + 2]);
            }
    }

    float* base = attn + ((size_t)(b * N_HEADS + h)) * N_SEQ * N_SEQ;
    const int g = lane >> 2, tg = lane & 3;
    #pragma unroll
    for (int mt = 0; mt < 4; mt++)
        #pragma unroll
        for (int nt = 0; nt < 4; nt++) {
            const int q = i * 128 + wm + mt * 16 + g;
            const int col = j * 128 + wn + nt * 8 + tg * 2;
            *(float2*)(base + (size_t)q * N_SEQ + col) =
                make_float2(c[mt][nt][0] * 0.125f, c[mt][nt][1] * 0.125f);
            *(float2*)(base + (size_t)(q + 8) * N_SEQ + col) =
                make_float2(c[mt][nt][2] * 0.125f, c[mt][nt][3] * 0.125f);
        }
}

// ---------------------------------------------------------------------------
// One-pass softmax; also emits split-bf16 P (Ph/Pl) for the causal tile span.
// ---------------------------------------------------------------------------
__global__ __launch_bounds__(256) void softmax1p(float* __restrict__ attn,
                                                 __nv_bfloat16* __restrict__ ph,
                                                 __nv_bfloat16* __restrict__ pl)
{
    const int n = blockIdx.x, h = blockIdx.y, b = blockIdx.z;
    const int tid = threadIdx.x;
    const size_t rowbase = ((size_t)(b * N_HEADS + h) * N_SEQ + n) * N_SEQ;
    float* row = attn + rowbase;

    __shared__ float red[256];
    const int P = n + 1, n4 = P >> 2, tail = P & 3;
    const int cover4 = (((P + 127) >> 7) << 5);   // float4 groups covering causal tiles

    float4 v[2];
    int cnt = 0;
    float lmax = -INFINITY;
    #pragma unroll
    for (int k = 0; k < 2; k++) {
        int m4 = tid + k * 256;
        if (m4 < n4) {
            float4 x = *(const float4*)&row[m4 * 4];
            v[cnt++] = x;
            lmax = fmaxf(lmax, fmaxf(fmaxf(x.x, x.y), fmaxf(x.z, x.w)));
        }
    }
    float tv = 0.f;
    const bool hasT = (tid < tail);
    if (hasT) { tv = row[n4 * 4 + tid]; lmax = fmaxf(lmax, tv); }

    red[tid] = lmax;
    __syncthreads();
    #pragma unroll
    for (int s = 128; s > 0; s >>= 1) {
        if (tid < s) red[tid] = fmaxf(red[tid], red[tid + s]);
        __syncthreads();
    }
    const float mx = red[0];
    __syncthreads();

    float ls = 0.f;
    for (int k = 0; k < cnt; k++)
        ls += __expf(v[k].x - mx) + __expf(v[k].y - mx) +
              __expf(v[k].z - mx) + __expf(v[k].w - mx);
    if (hasT) ls += __expf(tv - mx);
    red[tid] = ls;
    __syncthreads();
    #pragma unroll
    for (int s = 128; s > 0; s >>= 1) {
        if (tid < s) red[tid] += red[tid + s];
        __syncthreads();
    }
    const float inv = 1.f / red[0];

    cnt = 0;
    #pragma unroll
    for (int k = 0; k < 2; k++) {
        int m4 = tid + k * 256;
        float4 o;
        if (m4 < n4) {
            float4 x = v[cnt++];
            o.x = __expf(x.x - mx) * inv;
            o.y = __expf(x.y - mx) * inv;
            o.z = __expf(x.z - mx) * inv;
            o.w = __expf(x.w - mx) * inv;
        } else if (m4 == n4 && tail) {
            float4 x = *(const float4*)&row[m4 * 4];
            float xx[4] = {x.x, x.y, x.z, x.w};
            float oo[4];
            #pragma unroll
            for (int q = 0; q < 4; q++)
                oo[q] = (m4 * 4 + q < P) ? __expf(xx[q] - mx) * inv : 0.f;
            o = make_float4(oo[0], oo[1], oo[2], oo[3]);
        } else {
            o = make_float4(0.f, 0.f, 0.f, 0.f);
        }
        *(float4*)&row[m4 * 4] = o;

        if (m4 < cover4) {
            float oo[4] = {o.x, o.y, o.z, o.w};
            __nv_bfloat16 hh[4], ll[4];
            #pragma unroll
            for (int q = 0; q < 4; q++) bsplit(oo[q], hh[q], ll[q]);
            *(uint2*)&ph[rowbase + m4 * 4] = *(uint2*)hh;
            *(uint2*)&pl[rowbase + m4 * 4] = *(uint2*)ll;
        }
    }
}

// ---------------------------------------------------------------------------
// PV: ctx = P @ V; all operand tiles (Ph,Pl,Vh,Vl) pulled via cp.async.
// ---------------------------------------------------------------------------
#define LDP 136
#define SMEM_PV ((2 * 128 * LDP + 2 * 128 * LDT) * 2)   // 106496 B

__global__ __launch_bounds__(256) void pv_mma(const __nv_bfloat16* __restrict__ ph,
                                              const __nv_bfloat16* __restrict__ pl,
                                              const __nv_bfloat16* __restrict__ qh,
                                              const __nv_bfloat16* __restrict__ ql,
                                              __nv_bfloat16* __restrict__ ch,
                                              __nv_bfloat16* __restrict__ cl)
{
    const int i = NT128 - 1 - blockIdx.x;   // heavy first
    const int h = blockIdx.y, b = blockIdx.z;

    extern __shared__ __nv_bfloat16 sm[];
    __nv_bfloat16* Ph = sm;
    __nv_bfloat16* Pl = Ph + 128 * LDP;
    __nv_bfloat16* Vh = Pl + 128 * LDP;
    __nv_bfloat16* Vl = Vh + 128 * LDT;

    const int tid = threadIdx.x, lane = tid & 31, wid = tid >> 5;
    const int wm = (wid >> 1) * 32, wn = (wid & 1) * 32;
    const int lrow = lane & 15, lcol = (lane >> 4) * 8;

    const uint32_t sPh = smem_u32(Ph), sPl = smem_u32(Pl);
    const uint32_t sVh = smem_u32(Vh), sVl = smem_u32(Vl);

    const size_t pbase = ((size_t)(b * N_HEADS + h)) * N_SEQ * N_SEQ
                       + (size_t)i * 128 * N_SEQ;
    float c[2][4][4] = {};

    for (int j = 0; j <= i; j++) {
        if (j) __syncthreads();
        // P tiles (hi/lo): 128 rows x 16 16B-chunks each
        for (int e = tid; e < 2048; e += 256) {
            int r = e >> 4, cc = e & 15;
            uint32_t so = (uint32_t)(r * LDP + cc * 8) * 2;
            size_t ga = pbase + (size_t)r * N_SEQ + j * 128 + cc * 8;
            cpa16(sPh + so, ph + ga);
            cpa16(sPl + so, pl + ga);
        }
        // V tiles (hi/lo): 128 rows x 8 16B-chunks each (64 cols)
        for (int e = tid; e < 1024; e += 256) {
            int r = e >> 3, cc = e & 7;
            uint32_t so = (uint32_t)(r * LDT + cc * 8) * 2;
            size_t va = (size_t)(b * N_SEQ + j * 128 + r) * QKV_COLS + 2 * D_MODEL + h * 64 + cc * 8;
            cpa16(sVh + so, qh + va);
            cpa16(sVl + so, ql + va);
        }
        CP_COMMIT();
        CP_WAIT0();
        __syncthreads();

        #pragma unroll
        for (int kt = 0; kt < 8; kt++) {
            uint32_t ah[2][4], al[2][4], vh[2][4], vl[2][4];
            #pragma unroll
            for (int mt = 0; mt < 2; mt++) {
                uint32_t off = ((wm + mt * 16 + lrow) * LDP + kt * 16 + lcol) * 2;
                ldsm4(ah[mt], sPh + off);
                ldsm4(al[mt], sPl + off);
            }
            #pragma unroll
            for (int bt = 0; bt < 2; bt++) {
                uint32_t off = ((kt * 16 + lrow) * LDT + wn + bt * 16 + lcol) * 2;
                ldsm4t(vh[bt], sVh + off);
                ldsm4t(vl[bt], sVl + off);
            }
            #pragma unroll
            for (int mt = 0; mt < 2; mt++)
                #pragma unroll
                for (int nt = 0; nt < 4; nt++) {
                    const int bt = nt >> 1, s = (nt & 1) * 2;
                    mma16816(c[mt][nt], ah[mt], vh[bt][s], vh[bt][s + 1]);
                    mma16816(c[mt][nt], al[mt], vh[bt][s], vh[bt][s + 1]);
                    mma16816(c[mt][nt], ah[mt], vl[bt][s], vl[bt][s + 1]);
                }
        }
    }

    const int g = lane >> 2, tg = lane & 3;
    #pragma unroll
    for (int mt = 0; mt < 2; mt++)
        #pragma unroll
        for (int nt = 0; nt < 4; nt++) {
            const int q = i * 128 + wm + mt * 16 + g;
            const int d = wn + nt * 8 + tg * 2;
            __nv_bfloat16 h0, l0, h1, l1;
            bsplit(c[mt][nt][0], h0, l0);
            bsplit(c[mt][nt][1], h1, l1);
            __nv_bfloat162 hh; hh.x = h0; hh.y = h1;
            __nv_bfloat162 ll; ll.x = l0; ll.y = l1;
            *(__nv_bfloat162*)(ch + (size_t)(b * N_SEQ + q) * D_MODEL + h * 64 + d) = hh;
            *(__nv_bfloat162*)(cl + (size_t)(b * N_SEQ + q) * D_MODEL + h * 64 + d) = ll;
            bsplit(c[mt][nt][2], h0, l0);
            bsplit(c[mt][nt][3], h1, l1);
            hh.x = h0; hh.y = h1; ll.x = l0; ll.y = l1;
            *(__nv_bfloat162*)(ch + (size_t)(b * N_SEQ + q + 8) * D_MODEL + h * 64 + d) = hh;
            *(__nv_bfloat162*)(cl + (size_t)(b * N_SEQ + q + 8) * D_MODEL + h * 64 + d) = ll;
        }
}

// ---------------------------------------------------------------------------
extern "C" void kernel_launch(void* const* d_in, const int* in_sizes, int n_in,
                              void* d_out, int out_size)
{
    const float* x     = (const float*)d_in[0];
    const float* W_qkv = (const float*)d_in[1];
    const float* W_out = (const float*)d_in[2];
    float* out = (float*)d_out;

    float* attn_scratch;
    __nv_bfloat16 *php, *plp, *xh, *xl, *qkvh, *qkvl, *ch, *cl, *wqh, *wql, *woh, *wol;
    cudaGetSymbolAddress((void**)&attn_scratch, g_attn);
    cudaGetSymbolAddress((void**)&php, g_ph);
    cudaGetSymbolAddress((void**)&plp, g_pl);
    cudaGetSymbolAddress((void**)&xh, g_xh);
    cudaGetSymbolAddress((void**)&xl, g_xl);
    cudaGetSymbolAddress((void**)&qkvh, g_qkvh);
    cudaGetSymbolAddress((void**)&qkvl, g_qkvl);
    cudaGetSymbolAddress((void**)&ch, g_ch);
    cudaGetSymbolAddress((void**)&cl, g_cl);
    cudaGetSymbolAddress((void**)&wqh, g_wqh);
    cudaGetSymbolAddress((void**)&wql, g_wql);
    cudaGetSymbolAddress((void**)&woh, g_woh);
    cudaGetSymbolAddress((void**)&wol, g_wol);

    cudaFuncSetAttribute(gemm_mma<true>,  cudaFuncAttributeMaxDynamicSharedMemorySize, SMEM_G);
    cudaFuncSetAttribute(gemm_mma<false>, cudaFuncAttributeMaxDynamicSharedMemorySize, SMEM_G);
    cudaFuncSetAttribute(scores_mma,      cudaFuncAttributeMaxDynamicSharedMemorySize, SMEM_S);
    cudaFuncSetAttribute(pv_mma,          cudaFuncAttributeMaxDynamicSharedMemorySize, SMEM_PV);

    const long long out_elems  = (long long)B_SZ * N_SEQ * D_MODEL;
    const long long attn_elems = (long long)B_SZ * N_HEADS * N_SEQ * N_SEQ;
    const int write_attn = ((long long)out_size >= out_elems + attn_elems) ? 1 : 0;
    float* attn_buf = write_attn ? (out + out_elems) : attn_scratch;

    // 0) prep
    split_kernel<<<(M_ROWS * D_MODEL) / 1024, 256>>>(x, xh, xl);
    {
        dim3 grid(QKV_COLS / 32, D_MODEL / 32);
        wtrans_split<<<grid, dim3(32, 8)>>>(W_qkv, wqh, wql, D_MODEL, QKV_COLS);
    }
    {
        dim3 grid(D_MODEL / 32, D_MODEL / 32);
        wtrans_split<<<grid, dim3(32, 8)>>>(W_out, woh, wol, D_MODEL, D_MODEL);
    }

    // 1) QKV projection -> split bf16 qkv
    {
        dim3 grid(QKV_COLS / 64, M_ROWS / 128);
        gemm_mma<true><<<grid, 128, SMEM_G>>>(xh, xl, wqh, wql,
                                              nullptr, qkvh, qkvl, QKV_COLS, D_MODEL);
    }
    // 2a) raw scores
    {
        dim3 grid(NPAIR128, N_HEADS, B_SZ);
        scores_mma<<<grid, 256, SMEM_S>>>(qkvh, qkvl, attn_buf);
    }
    // 2b) one-pass softmax -> attn (fp32) + Ph/Pl (split bf16, causal span)
    {
        dim3 grid(N_SEQ, N_HEADS, B_SZ);
        softmax1p<<<grid, 256>>>(attn_buf, php, plp);
    }
    // 2c) P @ V -> split bf16 ctx (pure cp.async -> mma loop)
    {
        dim3 grid(NT128, N_HEADS, B_SZ);
        pv_mma<<<grid, 256, SMEM_PV>>>(php, plp, qkvh, qkvl, ch, cl);
    }
    // 3) output projection -> fp32 out
    {
        dim3 grid(D_MODEL / 64, M_ROWS / 128);
        gemm_mma<false><<<grid, 128, SMEM_G>>>(ch, cl, woh, wol,
                                               out, nullptr, nullptr, D_MODEL, D_MODEL);
    }
}